// round 9
// baseline (speedup 1.0000x reference)
#include <cuda_runtime.h>
#include <math.h>

#define N_PTS 2048
#define B_SZ 4
#define NB (B_SZ * N_PTS)          // 8192 positions
#define KNN 20
#define PPOS (NB * KNN)            // 163840
#define HCH 512
#define NEG_SLOPE 0.2f

// ---------------- scratch (static device globals) ----------------
__device__ unsigned g_pd[B_SZ * N_PTS * N_PTS];  // 64 MB, ordered u32 keys
__device__ float  g_xx[NB];
__device__ int    g_idx[NB * KNN];
__device__ float  g_Xt[NB * 4];                 // pos-major x, padded stride 4
__device__ float  g_Ht[NB * HCH];               // pos-major features [bn][512]
__device__ float  g_Wpq[512 * 128];             // packed [W1 ; W2-W1]
__device__ float  g_PQ[512 * NB + 8];           // P rows then Q rows, o-major
__device__ float  g_M[256 * NB];                // maxP + Q per (o, bn)
__device__ float  g_Y5[1024 * NB];              // conv5 pre-BN output
__device__ double g_ps[1024 * 8], g_pq2[1024 * 8];  // BN partial sums (o, part)
__device__ float  g_scale[1024], g_shift[1024];
__device__ float  g_z[B_SZ * 2048];
__device__ float  g_e[2 * B_SZ * 10];

__device__ __forceinline__ unsigned fkey(float v) {
    unsigned u = __float_as_uint(v);
    return ((int)u < 0) ? ~u : (u | 0x80000000u);
}

// ---------------- build pos-major x with zero pad ----------------
__global__ void transpose_x(const float* __restrict__ x) {
    int i = blockIdx.x * 256 + threadIdx.x;
    if (i >= NB) return;
    int b = i >> 11, n = i & 2047;
    float4 v;
    v.x = x[(b * 3 + 0) * N_PTS + n];
    v.y = x[(b * 3 + 1) * N_PTS + n];
    v.z = x[(b * 3 + 2) * N_PTS + n];
    v.w = 0.f;
    *(float4*)&g_Xt[i * 4] = v;
}

// ---------------- xx[bn] = sum_c F[bn][c]^2 ----------------
__global__ void compute_xx(const float* __restrict__ F, int ldf, int K) {
    int i = blockIdx.x * 256 + threadIdx.x;
    if (i >= NB) return;
    const float* row = F + (size_t)i * ldf;
    float s = 0.f;
    for (int c = 0; c < K; c++) { float v = row[c]; s += v * v; }
    g_xx[i] = s;
}

// ---------------- pd GEMM: writes ordered u32 keys of 2*<F_n,F_m>-xx_n-xx_m ----------------
__global__ __launch_bounds__(256, 2) void pd_gemm2(const float* __restrict__ F, int ldf,
                                                   int rowLen, int K, size_t bstride) {
    __shared__ float As[2][16][132];
    __shared__ float Bs[2][16][132];
    int tid = threadIdx.x, tx = tid & 15, ty = tid >> 4;
    int n0 = blockIdx.y * 128, m0 = blockIdx.x * 128;
    int b = blockIdx.z;
    const float* Ab = F + (size_t)b * bstride + (size_t)n0 * ldf;
    const float* Bb = F + (size_t)b * bstride + (size_t)m0 * ldf;
    int k4 = (tid & 3) * 4, rowq = tid >> 2;
    int KIT = (K + 15) >> 4;
    float acc[8][8] = {};
    {
#pragma unroll
        for (int r = 0; r < 2; r++) {
            int rw = rowq + r * 64;
            float4 va = make_float4(0, 0, 0, 0), vb = make_float4(0, 0, 0, 0);
            if (k4 < rowLen) {
                va = *(const float4*)&Ab[(size_t)rw * ldf + k4];
                vb = *(const float4*)&Bb[(size_t)rw * ldf + k4];
            }
            As[0][k4 + 0][rw] = va.x; As[0][k4 + 1][rw] = va.y;
            As[0][k4 + 2][rw] = va.z; As[0][k4 + 3][rw] = va.w;
            Bs[0][k4 + 0][rw] = vb.x; Bs[0][k4 + 1][rw] = vb.y;
            Bs[0][k4 + 2][rw] = vb.z; Bs[0][k4 + 3][rw] = vb.w;
        }
    }
    __syncthreads();
    int buf = 0;
    for (int it = 0; it < KIT; ++it) {
        float4 ra[2], rb[2];
        bool more = (it + 1 < KIT);
        if (more) {
            int k0 = (it + 1) << 4;
#pragma unroll
            for (int r = 0; r < 2; r++) {
                int rw = rowq + r * 64;
                ra[r] = make_float4(0, 0, 0, 0);
                rb[r] = make_float4(0, 0, 0, 0);
                if (k0 + k4 < rowLen) {
                    ra[r] = *(const float4*)&Ab[(size_t)rw * ldf + k0 + k4];
                    rb[r] = *(const float4*)&Bb[(size_t)rw * ldf + k0 + k4];
                }
            }
        }
#pragma unroll
        for (int k = 0; k < 16; k++) {
            float4 a0 = *(const float4*)&As[buf][k][ty * 4];
            float4 a1 = *(const float4*)&As[buf][k][64 + ty * 4];
            float4 b0 = *(const float4*)&Bs[buf][k][tx * 4];
            float4 b1 = *(const float4*)&Bs[buf][k][64 + tx * 4];
            float av[8] = {a0.x, a0.y, a0.z, a0.w, a1.x, a1.y, a1.z, a1.w};
            float bv[8] = {b0.x, b0.y, b0.z, b0.w, b1.x, b1.y, b1.z, b1.w};
#pragma unroll
            for (int i = 0; i < 8; i++)
#pragma unroll
                for (int j = 0; j < 8; j++) acc[i][j] += av[i] * bv[j];
        }
        if (more) {
            int nb2 = buf ^ 1;
#pragma unroll
            for (int r = 0; r < 2; r++) {
                int rw = rowq + r * 64;
                As[nb2][k4 + 0][rw] = ra[r].x; As[nb2][k4 + 1][rw] = ra[r].y;
                As[nb2][k4 + 2][rw] = ra[r].z; As[nb2][k4 + 3][rw] = ra[r].w;
                Bs[nb2][k4 + 0][rw] = rb[r].x; Bs[nb2][k4 + 1][rw] = rb[r].y;
                Bs[nb2][k4 + 2][rw] = rb[r].z; Bs[nb2][k4 + 3][rw] = rb[r].w;
            }
            __syncthreads();
            buf = nb2;
        }
    }
    int mA = m0 + tx * 4, mB = m0 + 64 + tx * 4;
    float xmA[4], xmB[4];
#pragma unroll
    for (int j = 0; j < 4; j++) {
        xmA[j] = g_xx[b * N_PTS + mA + j];
        xmB[j] = g_xx[b * N_PTS + mB + j];
    }
#pragma unroll
    for (int i = 0; i < 8; i++) {
        int n = n0 + (i < 4 ? ty * 4 + i : 64 + ty * 4 + (i - 4));
        float xn = g_xx[b * N_PTS + n];
        uint4 o0, o1;
        o0.x = fkey(2.f * acc[i][0] - xn - xmA[0]);
        o0.y = fkey(2.f * acc[i][1] - xn - xmA[1]);
        o0.z = fkey(2.f * acc[i][2] - xn - xmA[2]);
        o0.w = fkey(2.f * acc[i][3] - xn - xmA[3]);
        o1.x = fkey(2.f * acc[i][4] - xn - xmB[0]);
        o1.y = fkey(2.f * acc[i][5] - xn - xmB[1]);
        o1.z = fkey(2.f * acc[i][6] - xn - xmB[2]);
        o1.w = fkey(2.f * acc[i][7] - xn - xmB[3]);
        size_t base = (size_t)b * N_PTS * N_PTS + (size_t)n * N_PTS;
        *(uint4*)&g_pd[base + mA] = o0;
        *(uint4*)&g_pd[base + mB] = o1;
    }
}

// ---------------- generic GEMM: C[m][n] = sum_k A[m][k]*B[n][k] (plain FFMA) ----------------
__global__ __launch_bounds__(256, 2) void sgemm_wn(const float* __restrict__ A, int lda,
                                                   int K, const float* __restrict__ B,
                                                   int ldb, int rowLenB,
                                                   float* __restrict__ C, int ldc) {
    __shared__ float As[2][16][132];
    __shared__ float Bs[2][16][132];
    int tid = threadIdx.x, tx = tid & 15, ty = tid >> 4;
    int n0 = blockIdx.x * 128, m0 = blockIdx.y * 128;
    const float* Ab = A + (size_t)m0 * lda;
    const float* Bb = B + (size_t)n0 * ldb;
    int k4 = (tid & 3) * 4, rowq = tid >> 2;
    int KIT = (K + 15) >> 4;
    float acc[8][8] = {};
    {
#pragma unroll
        for (int r = 0; r < 8; r++) {
            int m = tx + r * 16;
            As[0][ty][m] = (ty < K) ? Ab[(size_t)m * lda + ty] : 0.f;
        }
#pragma unroll
        for (int r = 0; r < 2; r++) {
            int rw = rowq + r * 64;
            float4 v = make_float4(0, 0, 0, 0);
            if (k4 < rowLenB) v = *(const float4*)&Bb[(size_t)rw * ldb + k4];
            Bs[0][k4 + 0][rw] = v.x; Bs[0][k4 + 1][rw] = v.y;
            Bs[0][k4 + 2][rw] = v.z; Bs[0][k4 + 3][rw] = v.w;
        }
    }
    __syncthreads();
    int buf = 0;
    for (int it = 0; it < KIT; ++it) {
        float ra[8];
        float4 rb[2];
        bool more = (it + 1 < KIT);
        if (more) {
            int k0 = (it + 1) << 4;
#pragma unroll
            for (int r = 0; r < 8; r++) {
                int m = tx + r * 16;
                ra[r] = (k0 + ty < K) ? Ab[(size_t)m * lda + k0 + ty] : 0.f;
            }
#pragma unroll
            for (int r = 0; r < 2; r++) {
                int rw = rowq + r * 64;
                rb[r] = make_float4(0, 0, 0, 0);
                if (k0 + k4 < rowLenB) rb[r] = *(const float4*)&Bb[(size_t)rw * ldb + k0 + k4];
            }
        }
#pragma unroll
        for (int k = 0; k < 16; k++) {
            float4 a0 = *(const float4*)&As[buf][k][ty * 4];
            float4 a1 = *(const float4*)&As[buf][k][64 + ty * 4];
            float4 b0 = *(const float4*)&Bs[buf][k][tx * 4];
            float4 b1 = *(const float4*)&Bs[buf][k][64 + tx * 4];
            float av[8] = {a0.x, a0.y, a0.z, a0.w, a1.x, a1.y, a1.z, a1.w};
            float bv[8] = {b0.x, b0.y, b0.z, b0.w, b1.x, b1.y, b1.z, b1.w};
#pragma unroll
            for (int i = 0; i < 8; i++)
#pragma unroll
                for (int j = 0; j < 8; j++) acc[i][j] += av[i] * bv[j];
        }
        if (more) {
            int nb2 = buf ^ 1;
#pragma unroll
            for (int r = 0; r < 8; r++) As[nb2][ty][tx + r * 16] = ra[r];
#pragma unroll
            for (int r = 0; r < 2; r++) {
                int rw = rowq + r * 64;
                Bs[nb2][k4 + 0][rw] = rb[r].x; Bs[nb2][k4 + 1][rw] = rb[r].y;
                Bs[nb2][k4 + 2][rw] = rb[r].z; Bs[nb2][k4 + 3][rw] = rb[r].w;
            }
            __syncthreads();
            buf = nb2;
        }
    }
#pragma unroll
    for (int i = 0; i < 8; i++) {
        int m = m0 + (i < 4 ? ty * 4 + i : 64 + ty * 4 + (i - 4));
        float4 v0 = make_float4(acc[i][0], acc[i][1], acc[i][2], acc[i][3]);
        float4 v1 = make_float4(acc[i][4], acc[i][5], acc[i][6], acc[i][7]);
        *(float4*)&C[(size_t)m * ldc + n0 + tx * 4] = v0;
        *(float4*)&C[(size_t)m * ldc + n0 + 64 + tx * 4] = v1;
    }
}

// ---------------- top-20 per row: two-level bucket select ----------------
// Level 1 on key bits [31:24], level 2 refines the threshold bucket on bits
// [23:16]. Candidates (16-bit-prefix ties) go to a 256-entry list; overflow
// falls back to an exact block-wide argmax over register values. Selected SET
// is unordered (downstream reductions are permutation-invariant).
__global__ __launch_bounds__(256) void topk_kernel() {
    int r = blockIdx.x;
    const unsigned* row = g_pd + (size_t)r * N_PTS;
    __shared__ int hist[256];
    __shared__ unsigned long long cand[256];
    __shared__ unsigned long long red[256];
    __shared__ int sB1, sC1, sP, cnts[2];
    int tid = threadIdx.x;
    hist[tid] = 0;
    if (tid < 2) cnts[tid] = 0;
    __syncthreads();
    unsigned vals[8];
#pragma unroll
    for (int i = 0; i < 8; i++) {
        unsigned u = row[tid + i * 256];
        vals[i] = u;
        atomicAdd(&hist[u >> 24], 1);
    }
    __syncthreads();
    if (tid == 0) {
        int c = 0, b = 255;
        while (c + hist[b] < KNN) { c += hist[b]; b--; }
        sB1 = b;
        sC1 = c;
    }
    __syncthreads();
    unsigned B1 = (unsigned)sB1;
    hist[tid] = 0;
    __syncthreads();
#pragma unroll
    for (int i = 0; i < 8; i++) {
        unsigned u = vals[i];
        if ((u >> 24) == B1) atomicAdd(&hist[(u >> 16) & 255], 1);
    }
    __syncthreads();
    if (tid == 0) {
        int c = sC1, b = 255;
        while (c + hist[b] < KNN) { c += hist[b]; b--; }
        sP = (int)((B1 << 8) | (unsigned)b);
    }
    __syncthreads();
    unsigned P = (unsigned)sP;
#pragma unroll
    for (int i = 0; i < 8; i++) {
        int m = tid + i * 256;
        unsigned p16 = vals[i] >> 16;
        if (p16 > P) {
            int slot = atomicAdd(&cnts[0], 1);
            g_idx[r * KNN + slot] = m;
        } else if (p16 == P) {
            int slot = atomicAdd(&cnts[1], 1);
            if (slot < 256)
                cand[slot] =
                    ((unsigned long long)vals[i] << 32) | (unsigned)(0xFFFFFFFFu - m);
        }
    }
    __syncthreads();
    int base = cnts[0], cnt = cnts[1], need = KNN - base;
    if (cnt <= 256) {
        if (tid < 32) {
            for (int it = 0; it < need; it++) {
                unsigned long long best = 0;
                for (int j = tid; j < cnt; j += 32) {
                    unsigned long long k = cand[j];
                    if (k > best) best = k;
                }
#pragma unroll
                for (int s = 16; s; s >>= 1) {
                    unsigned long long o = __shfl_xor_sync(0xffffffffu, best, s);
                    if (o > best) best = o;
                }
                if (tid == 0)
                    g_idx[r * KNN + base + it] =
                        (int)(0xFFFFFFFFu - (unsigned)(best & 0xFFFFFFFFull));
                for (int j = tid; j < cnt; j += 32)
                    if (cand[j] == best) cand[j] = 0;
                __syncwarp();
            }
        }
    } else {
        // exact fallback: block-wide iterative argmax over register values
        bool act[8];
#pragma unroll
        for (int i = 0; i < 8; i++) act[i] = ((vals[i] >> 16) == P);
        for (int it = 0; it < need; it++) {
            unsigned long long best = 0;
#pragma unroll
            for (int i = 0; i < 8; i++)
                if (act[i]) {
                    unsigned long long k = ((unsigned long long)vals[i] << 32) |
                                           (unsigned)(0xFFFFFFFFu - (tid + i * 256));
                    if (k > best) best = k;
                }
            red[tid] = best;
            __syncthreads();
            for (int st = 128; st; st >>= 1) {
                if (tid < st && red[tid + st] > red[tid]) red[tid] = red[tid + st];
                __syncthreads();
            }
            unsigned long long top = red[0];
            int midx = (int)(0xFFFFFFFFu - (unsigned)(top & 0xFFFFFFFFull));
            if (tid == 0) g_idx[r * KNN + base + it] = midx;
            if ((midx & 255) == tid) act[midx >> 8] = false;
            __syncthreads();
        }
    }
}

// ---------------- pack [W1 ; W2-W1] ----------------
__global__ void build_wpq(const float* __restrict__ W, int Cout, int Cin) {
    int i = blockIdx.x * 256 + threadIdx.x;
    if (i >= Cout * Cin) return;
    int o = i / Cin, c = i - o * Cin;
    float w1 = W[(size_t)o * 2 * Cin + c];
    float w2 = W[(size_t)o * 2 * Cin + Cin + c];
    g_Wpq[(size_t)o * Cin + c] = w1;
    g_Wpq[(size_t)(Cout + o) * Cin + c] = w2 - w1;
}

// ---------------- neighbor reduce: partial stats + M = max_k P[nb] + Q ----------------
__global__ void nbr_reduce(int Cout) {
    int o = blockIdx.x, b = blockIdx.y;
    __shared__ float sp[N_PTS];
    __shared__ double rs1[256], rs2[256];
    int tid = threadIdx.x;
    const float* Prow = g_PQ + (size_t)o * NB + b * N_PTS;
    const float* Qrow = g_PQ + (size_t)(Cout + o) * NB + b * N_PTS;
    for (int i = tid; i < N_PTS; i += 256) sp[i] = Prow[i];
    __syncthreads();
    double s1 = 0.0, s2 = 0.0;
    for (int n = tid; n < N_PTS; n += 256) {
        const int* ip = g_idx + (size_t)(b * N_PTS + n) * KNN;
        float mx = -1e30f, su = 0.f, su2 = 0.f;
#pragma unroll
        for (int k = 0; k < KNN; k++) {
            float p = sp[ip[k]];
            mx = fmaxf(mx, p);
            su += p;
            su2 += p * p;
        }
        float q = Qrow[n];
        g_M[(size_t)o * NB + b * N_PTS + n] = mx + q;
        s1 += (double)su + 20.0 * (double)q;
        s2 += (double)su2 + 2.0 * (double)q * (double)su + 20.0 * (double)q * (double)q;
    }
    rs1[tid] = s1;
    rs2[tid] = s2;
    __syncthreads();
    for (int st = 128; st; st >>= 1) {
        if (tid < st) { rs1[tid] += rs1[tid + st]; rs2[tid] += rs2[tid + st]; }
        __syncthreads();
    }
    if (!tid) {
        g_ps[o * 4 + b] = rs1[0];
        g_pq2[o * 4 + b] = rs2[0];
    }
}

__global__ void finalize_bn(const float* __restrict__ gam, const float* __restrict__ bet,
                            int Cout, double cnt, int nparts) {
    int o = blockIdx.x * 256 + threadIdx.x;
    if (o >= Cout) return;
    double s = 0.0, q = 0.0;
    for (int j = 0; j < nparts; j++) {
        s += g_ps[o * nparts + j];
        q += g_pq2[o * nparts + j];
    }
    double m = s / cnt;
    double v = q / cnt - m * m;
    float sc = (float)((double)gam[o] / sqrt(v + 1e-5));
    g_scale[o] = sc;
    g_shift[o] = bet[o] - (float)m * sc;
}

// ---------------- apply BN+LReLU to M -> Ht (pos-major) ----------------
__global__ void apply_bn(int Cout, int dstoff) {
    int bn = blockIdx.x;
    for (int o = threadIdx.x; o < Cout; o += blockDim.x) {
        float v = g_M[(size_t)o * NB + bn] * g_scale[o] + g_shift[o];
        v = v > 0.f ? v : NEG_SLOPE * v;
        g_Ht[(size_t)bn * HCH + dstoff + o] = v;
    }
}

// ---------------- conv5 partial stats ----------------
__global__ void stats_y5() {
    int o = blockIdx.x;
    size_t base = (size_t)o * NB + blockIdx.y * 1024;
    double s = 0.0, q = 0.0;
    for (int i = threadIdx.x; i < 1024; i += 256) {
        double v = (double)g_Y5[base + i];
        s += v;
        q += v * v;
    }
    __shared__ double sh[256];
    int tid = threadIdx.x;
    sh[tid] = s;
    __syncthreads();
    for (int st = 128; st; st >>= 1) {
        if (tid < st) sh[tid] += sh[tid + st];
        __syncthreads();
    }
    double ts = sh[0];
    __syncthreads();
    sh[tid] = q;
    __syncthreads();
    for (int st = 128; st; st >>= 1) {
        if (tid < st) sh[tid] += sh[tid + st];
        __syncthreads();
    }
    if (!tid) {
        g_ps[o * 8 + blockIdx.y] = ts;
        g_pq2[o * 8 + blockIdx.y] = sh[0];
    }
}

// ---------------- conv5 BN + LReLU + max & mean over N -> z ----------------
__global__ void zmaxmean_kernel() {
    int o = blockIdx.x, b = blockIdx.y;
    const float* row = g_Y5 + (size_t)o * NB + (size_t)b * N_PTS;
    float sc = g_scale[o], sh = g_shift[o];
    float mx = -1e30f, sm = 0.f;
    for (int n = threadIdx.x; n < N_PTS; n += 256) {
        float v = row[n] * sc + sh;
        v = v > 0.f ? v : NEG_SLOPE * v;
        mx = fmaxf(mx, v);
        sm += v;
    }
    __shared__ float smx[256];
    __shared__ float ssm[256];
    int tid = threadIdx.x;
    smx[tid] = mx;
    ssm[tid] = sm;
    __syncthreads();
    for (int st = 128; st; st >>= 1) {
        if (tid < st) {
            smx[tid] = fmaxf(smx[tid], smx[tid + st]);
            ssm[tid] += ssm[tid + st];
        }
        __syncthreads();
    }
    if (!tid) {
        g_z[b * 2048 + o] = smx[0];
        g_z[b * 2048 + 1024 + o] = ssm[0] * (1.f / 2048.f);
    }
}

// ---------------- MLP head ----------------
__global__ void head_kernel(const float* __restrict__ lw1, const float* __restrict__ lb1,
                            const float* __restrict__ lw2, const float* __restrict__ lb2,
                            const float* __restrict__ lw3, const float* __restrict__ lb3,
                            int slot, float* __restrict__ out) {
    int b = blockIdx.x, tid = threadIdx.x;
    __shared__ float zs[2048];
    __shared__ float z1[256];
    __shared__ float z2[64];
    for (int i = tid; i < 2048; i += 256) zs[i] = g_z[b * 2048 + i];
    __syncthreads();
    {
        float a = lb1[tid];
        const float* wr = lw1 + (size_t)tid * 2048;
        for (int c = 0; c < 2048; c++) a += wr[c] * zs[c];
        z1[tid] = a;
    }
    __syncthreads();
    if (tid < 64) {
        float a = lb2[tid];
        const float* wr = lw2 + (size_t)tid * 256;
        for (int c = 0; c < 256; c++) a += wr[c] * z1[c];
        z2[tid] = a;
    }
    __syncthreads();
    if (tid < 10) {
        float a = lb3[tid];
        const float* wr = lw3 + (size_t)tid * 64;
        for (int c = 0; c < 64; c++) a += wr[c] * z2[c];
        g_e[slot * 40 + b * 10 + tid] = a;
        out[6404 + slot * 40 + b * 10 + tid] = a;
    }
}

// ---------------- cluster assignment ----------------
__global__ void cluster_kernel(const float* __restrict__ cw, int slot,
                               float* __restrict__ out) {
    int b = blockIdx.x, j = threadIdx.x;
    __shared__ float es[10];
    __shared__ float red[1024];
    if (j < 10) es[j] = g_e[slot * 40 + b * 10 + j];
    __syncthreads();
    float xd = 0.f, qn = 0.f;
    if (j < 800) {
#pragma unroll
        for (int t = 0; t < 10; t++) {
            float d = es[t] - cw[j * 10 + t];
            xd += d * d;
        }
        qn = 1.f / (1.f + xd);
    }
    red[j] = qn;
    __syncthreads();
    for (int st = 512; st; st >>= 1) {
        if (j < st) red[j] += red[j + st];
        __syncthreads();
    }
    float tot = red[0];
    if (j < 800) {
        out[4 + slot * 3200 + b * 800 + j] = qn / tot;
        if (!slot) out[6484 + b * 800 + j] = xd;
    }
}

__global__ void sim_kernel(float* __restrict__ out) {
    int b = threadIdx.x;
    if (b < 4) {
        float s = 0.f;
        for (int j = 0; j < 10; j++) {
            float d = g_e[b * 10 + j] - g_e[40 + b * 10 + j] + 1e-6f;
            s += d * d;
        }
        out[b] = sqrtf(s);
    }
}

// ---------------- host orchestration ----------------
extern "C" void kernel_launch(void* const* d_in, const int* in_sizes, int n_in,
                              void* d_out, int out_size) {
    const float* x1 = (const float*)d_in[0];
    const float* x2 = (const float*)d_in[1];
    const float* Wl[4] = {(const float*)d_in[2], (const float*)d_in[5],
                          (const float*)d_in[8], (const float*)d_in[11]};
    const float* Gl[4] = {(const float*)d_in[3], (const float*)d_in[6],
                          (const float*)d_in[9], (const float*)d_in[12]};
    const float* Bl[4] = {(const float*)d_in[4], (const float*)d_in[7],
                          (const float*)d_in[10], (const float*)d_in[13]};
    const float* w5 = (const float*)d_in[14];
    const float* g5 = (const float*)d_in[15];
    const float* b5 = (const float*)d_in[16];
    const float* lw1 = (const float*)d_in[17];
    const float* lb1 = (const float*)d_in[18];
    const float* lw2 = (const float*)d_in[19];
    const float* lb2 = (const float*)d_in[20];
    const float* lw3 = (const float*)d_in[21];
    const float* lb3 = (const float*)d_in[22];
    const float* cw = (const float*)d_in[23];
    float* out = (float*)d_out;

    const int Cin[4] = {3, 64, 64, 128};
    const int Cout[4] = {64, 64, 128, 256};
    const int choff[4] = {0, 0, 64, 128};
    const int dstoff[4] = {0, 64, 128, 256};

    float* xtp = nullptr;
    float* htp = nullptr;
    float* wpq = nullptr;
    float* pq = nullptr;
    float* y5 = nullptr;
    cudaGetSymbolAddress((void**)&xtp, g_Xt);
    cudaGetSymbolAddress((void**)&htp, g_Ht);
    cudaGetSymbolAddress((void**)&wpq, g_Wpq);
    cudaGetSymbolAddress((void**)&pq, g_PQ);
    cudaGetSymbolAddress((void**)&y5, g_Y5);

    for (int s = 0; s < 2; s++) {
        const float* x = s ? x2 : x1;
        transpose_x<<<NB / 256, 256>>>(x);
        for (int l = 0; l < 4; l++) {
            const float* F = (l == 0) ? xtp : (htp + choff[l]);
            int ldf = (l == 0) ? 4 : HCH;
            int rowLen = (l == 0) ? 4 : Cin[l];
            size_t bstride = (size_t)N_PTS * ldf;
            compute_xx<<<NB / 256, 256>>>(F, ldf, Cin[l]);
            pd_gemm2<<<dim3(16, 16, B_SZ), 256>>>(F, ldf, rowLen, Cin[l], bstride);
            topk_kernel<<<NB, 256>>>();
            build_wpq<<<(Cout[l] * Cin[l] + 255) / 256, 256>>>(Wl[l], Cout[l], Cin[l]);
            sgemm_wn<<<dim3(NB / 128, 2 * Cout[l] / 128), 256>>>(wpq, Cin[l], Cin[l], F,
                                                                 ldf, rowLen, pq, NB);
            nbr_reduce<<<dim3(Cout[l], B_SZ), 256>>>(Cout[l]);
            finalize_bn<<<1, 256>>>(Gl[l], Bl[l], Cout[l], (double)PPOS, 4);
            apply_bn<<<NB, 256>>>(Cout[l], dstoff[l]);
        }
        sgemm_wn<<<dim3(NB / 128, 1024 / 128), 256>>>(w5, HCH, HCH, htp, HCH, HCH, y5,
                                                      NB);
        stats_y5<<<dim3(1024, 8), 256>>>();
        finalize_bn<<<4, 256>>>(g5, b5, 1024, (double)NB, 8);
        zmaxmean_kernel<<<dim3(1024, 4), 256>>>();
        head_kernel<<<4, 256>>>(lw1, lb1, lw2, lb2, lw3, lb3, s, out);
        cluster_kernel<<<4, 1024>>>(cw, s, out);
    }
    sim_kernel<<<1, 32>>>(out);
}

// round 10
// speedup vs baseline: 1.0031x; 1.0031x over previous
#include <cuda_runtime.h>
#include <math.h>

#define N_PTS 2048
#define B_SZ 4
#define NB (B_SZ * N_PTS)          // 8192 positions
#define KNN 20
#define PPOS (NB * KNN)            // 163840
#define HCH 512
#define NEG_SLOPE 0.2f

// ---------------- scratch (static device globals) ----------------
__device__ unsigned g_pd[B_SZ * N_PTS * N_PTS];  // 64 MB, ordered u32 keys
__device__ float  g_xx[NB];
__device__ int    g_idx[NB * KNN];
__device__ float  g_Xt[NB * 4];                 // pos-major x, padded stride 4
__device__ float  g_Ht[NB * HCH];               // pos-major features [bn][512]
__device__ float  g_Wpq[512 * 128];             // packed [W1 ; W2-W1]
__device__ float  g_PQ[512 * NB + 8];           // P rows then Q rows, o-major
__device__ float  g_M[256 * NB];                // maxP + Q per (o, bn)
__device__ float  g_Y5[1024 * NB];              // conv5 pre-BN output
__device__ double g_ps[1024 * 8], g_pq2[1024 * 8];  // BN partial sums (o, part)
__device__ float  g_scale[1024], g_shift[1024];
__device__ float  g_z[B_SZ * 2048];
__device__ float  g_e[2 * B_SZ * 10];

__device__ __forceinline__ unsigned fkey(float v) {
    unsigned u = __float_as_uint(v);
    return ((int)u < 0) ? ~u : (u | 0x80000000u);
}

// ---------------- build pos-major x with zero pad ----------------
__global__ void transpose_x(const float* __restrict__ x) {
    int i = blockIdx.x * 256 + threadIdx.x;
    if (i >= NB) return;
    int b = i >> 11, n = i & 2047;
    float4 v;
    v.x = x[(b * 3 + 0) * N_PTS + n];
    v.y = x[(b * 3 + 1) * N_PTS + n];
    v.z = x[(b * 3 + 2) * N_PTS + n];
    v.w = 0.f;
    *(float4*)&g_Xt[i * 4] = v;
}

// ---------------- xx[bn] = sum_c F[bn][c]^2 ----------------
__global__ void compute_xx(const float* __restrict__ F, int ldf, int K) {
    int i = blockIdx.x * 256 + threadIdx.x;
    if (i >= NB) return;
    const float* row = F + (size_t)i * ldf;
    float s = 0.f;
    for (int c = 0; c < K; c++) { float v = row[c]; s += v * v; }
    g_xx[i] = s;
}

// ---------------- pd GEMM: writes ordered u32 keys of 2*<F_n,F_m>-xx_n-xx_m ----------------
__global__ __launch_bounds__(256, 2) void pd_gemm2(const float* __restrict__ F, int ldf,
                                                   int rowLen, int K, size_t bstride) {
    __shared__ float As[2][16][132];
    __shared__ float Bs[2][16][132];
    int tid = threadIdx.x, tx = tid & 15, ty = tid >> 4;
    int n0 = blockIdx.y * 128, m0 = blockIdx.x * 128;
    int b = blockIdx.z;
    const float* Ab = F + (size_t)b * bstride + (size_t)n0 * ldf;
    const float* Bb = F + (size_t)b * bstride + (size_t)m0 * ldf;
    int k4 = (tid & 3) * 4, rowq = tid >> 2;
    int KIT = (K + 15) >> 4;
    float acc[8][8] = {};
    {
#pragma unroll
        for (int r = 0; r < 2; r++) {
            int rw = rowq + r * 64;
            float4 va = make_float4(0, 0, 0, 0), vb = make_float4(0, 0, 0, 0);
            if (k4 < rowLen) {
                va = *(const float4*)&Ab[(size_t)rw * ldf + k4];
                vb = *(const float4*)&Bb[(size_t)rw * ldf + k4];
            }
            As[0][k4 + 0][rw] = va.x; As[0][k4 + 1][rw] = va.y;
            As[0][k4 + 2][rw] = va.z; As[0][k4 + 3][rw] = va.w;
            Bs[0][k4 + 0][rw] = vb.x; Bs[0][k4 + 1][rw] = vb.y;
            Bs[0][k4 + 2][rw] = vb.z; Bs[0][k4 + 3][rw] = vb.w;
        }
    }
    __syncthreads();
    int buf = 0;
    for (int it = 0; it < KIT; ++it) {
        float4 ra[2], rb[2];
        bool more = (it + 1 < KIT);
        if (more) {
            int k0 = (it + 1) << 4;
#pragma unroll
            for (int r = 0; r < 2; r++) {
                int rw = rowq + r * 64;
                ra[r] = make_float4(0, 0, 0, 0);
                rb[r] = make_float4(0, 0, 0, 0);
                if (k0 + k4 < rowLen) {
                    ra[r] = *(const float4*)&Ab[(size_t)rw * ldf + k0 + k4];
                    rb[r] = *(const float4*)&Bb[(size_t)rw * ldf + k0 + k4];
                }
            }
        }
#pragma unroll
        for (int k = 0; k < 16; k++) {
            float4 a0 = *(const float4*)&As[buf][k][ty * 4];
            float4 a1 = *(const float4*)&As[buf][k][64 + ty * 4];
            float4 b0 = *(const float4*)&Bs[buf][k][tx * 4];
            float4 b1 = *(const float4*)&Bs[buf][k][64 + tx * 4];
            float av[8] = {a0.x, a0.y, a0.z, a0.w, a1.x, a1.y, a1.z, a1.w};
            float bv[8] = {b0.x, b0.y, b0.z, b0.w, b1.x, b1.y, b1.z, b1.w};
#pragma unroll
            for (int i = 0; i < 8; i++)
#pragma unroll
                for (int j = 0; j < 8; j++) acc[i][j] += av[i] * bv[j];
        }
        if (more) {
            int nb2 = buf ^ 1;
#pragma unroll
            for (int r = 0; r < 2; r++) {
                int rw = rowq + r * 64;
                As[nb2][k4 + 0][rw] = ra[r].x; As[nb2][k4 + 1][rw] = ra[r].y;
                As[nb2][k4 + 2][rw] = ra[r].z; As[nb2][k4 + 3][rw] = ra[r].w;
                Bs[nb2][k4 + 0][rw] = rb[r].x; Bs[nb2][k4 + 1][rw] = rb[r].y;
                Bs[nb2][k4 + 2][rw] = rb[r].z; Bs[nb2][k4 + 3][rw] = rb[r].w;
            }
            __syncthreads();
            buf = nb2;
        }
    }
    int mA = m0 + tx * 4, mB = m0 + 64 + tx * 4;
    float xmA[4], xmB[4];
#pragma unroll
    for (int j = 0; j < 4; j++) {
        xmA[j] = g_xx[b * N_PTS + mA + j];
        xmB[j] = g_xx[b * N_PTS + mB + j];
    }
#pragma unroll
    for (int i = 0; i < 8; i++) {
        int n = n0 + (i < 4 ? ty * 4 + i : 64 + ty * 4 + (i - 4));
        float xn = g_xx[b * N_PTS + n];
        uint4 o0, o1;
        o0.x = fkey(2.f * acc[i][0] - xn - xmA[0]);
        o0.y = fkey(2.f * acc[i][1] - xn - xmA[1]);
        o0.z = fkey(2.f * acc[i][2] - xn - xmA[2]);
        o0.w = fkey(2.f * acc[i][3] - xn - xmA[3]);
        o1.x = fkey(2.f * acc[i][4] - xn - xmB[0]);
        o1.y = fkey(2.f * acc[i][5] - xn - xmB[1]);
        o1.z = fkey(2.f * acc[i][6] - xn - xmB[2]);
        o1.w = fkey(2.f * acc[i][7] - xn - xmB[3]);
        size_t base = (size_t)b * N_PTS * N_PTS + (size_t)n * N_PTS;
        *(uint4*)&g_pd[base + mA] = o0;
        *(uint4*)&g_pd[base + mB] = o1;
    }
}

// ---------------- generic GEMM: C[m][n] = sum_k A[m][k]*B[n][k] (plain FFMA) ----------------
__global__ __launch_bounds__(256, 2) void sgemm_wn(const float* __restrict__ A, int lda,
                                                   int K, const float* __restrict__ B,
                                                   int ldb, int rowLenB,
                                                   float* __restrict__ C, int ldc) {
    __shared__ float As[2][16][132];
    __shared__ float Bs[2][16][132];
    int tid = threadIdx.x, tx = tid & 15, ty = tid >> 4;
    int n0 = blockIdx.x * 128, m0 = blockIdx.y * 128;
    const float* Ab = A + (size_t)m0 * lda;
    const float* Bb = B + (size_t)n0 * ldb;
    int k4 = (tid & 3) * 4, rowq = tid >> 2;
    int KIT = (K + 15) >> 4;
    float acc[8][8] = {};
    {
#pragma unroll
        for (int r = 0; r < 8; r++) {
            int m = tx + r * 16;
            As[0][ty][m] = (ty < K) ? Ab[(size_t)m * lda + ty] : 0.f;
        }
#pragma unroll
        for (int r = 0; r < 2; r++) {
            int rw = rowq + r * 64;
            float4 v = make_float4(0, 0, 0, 0);
            if (k4 < rowLenB) v = *(const float4*)&Bb[(size_t)rw * ldb + k4];
            Bs[0][k4 + 0][rw] = v.x; Bs[0][k4 + 1][rw] = v.y;
            Bs[0][k4 + 2][rw] = v.z; Bs[0][k4 + 3][rw] = v.w;
        }
    }
    __syncthreads();
    int buf = 0;
    for (int it = 0; it < KIT; ++it) {
        float ra[8];
        float4 rb[2];
        bool more = (it + 1 < KIT);
        if (more) {
            int k0 = (it + 1) << 4;
#pragma unroll
            for (int r = 0; r < 8; r++) {
                int m = tx + r * 16;
                ra[r] = (k0 + ty < K) ? Ab[(size_t)m * lda + k0 + ty] : 0.f;
            }
#pragma unroll
            for (int r = 0; r < 2; r++) {
                int rw = rowq + r * 64;
                rb[r] = make_float4(0, 0, 0, 0);
                if (k0 + k4 < rowLenB) rb[r] = *(const float4*)&Bb[(size_t)rw * ldb + k0 + k4];
            }
        }
#pragma unroll
        for (int k = 0; k < 16; k++) {
            float4 a0 = *(const float4*)&As[buf][k][ty * 4];
            float4 a1 = *(const float4*)&As[buf][k][64 + ty * 4];
            float4 b0 = *(const float4*)&Bs[buf][k][tx * 4];
            float4 b1 = *(const float4*)&Bs[buf][k][64 + tx * 4];
            float av[8] = {a0.x, a0.y, a0.z, a0.w, a1.x, a1.y, a1.z, a1.w};
            float bv[8] = {b0.x, b0.y, b0.z, b0.w, b1.x, b1.y, b1.z, b1.w};
#pragma unroll
            for (int i = 0; i < 8; i++)
#pragma unroll
                for (int j = 0; j < 8; j++) acc[i][j] += av[i] * bv[j];
        }
        if (more) {
            int nb2 = buf ^ 1;
#pragma unroll
            for (int r = 0; r < 8; r++) As[nb2][ty][tx + r * 16] = ra[r];
#pragma unroll
            for (int r = 0; r < 2; r++) {
                int rw = rowq + r * 64;
                Bs[nb2][k4 + 0][rw] = rb[r].x; Bs[nb2][k4 + 1][rw] = rb[r].y;
                Bs[nb2][k4 + 2][rw] = rb[r].z; Bs[nb2][k4 + 3][rw] = rb[r].w;
            }
            __syncthreads();
            buf = nb2;
        }
    }
#pragma unroll
    for (int i = 0; i < 8; i++) {
        int m = m0 + (i < 4 ? ty * 4 + i : 64 + ty * 4 + (i - 4));
        float4 v0 = make_float4(acc[i][0], acc[i][1], acc[i][2], acc[i][3]);
        float4 v1 = make_float4(acc[i][4], acc[i][5], acc[i][6], acc[i][7]);
        *(float4*)&C[(size_t)m * ldc + n0 + tx * 4] = v0;
        *(float4*)&C[(size_t)m * ldc + n0 + 64 + tx * 4] = v1;
    }
}

// ---------------- top-20 per row via bucket select (round-8 version, measured 68us) ----------------
// Selected SET unordered (downstream reductions are permutation-invariant).
__global__ __launch_bounds__(256) void topk_kernel() {
    int r = blockIdx.x;
    const unsigned* row = g_pd + (size_t)r * N_PTS;
    __shared__ unsigned long long cand[N_PTS];
    __shared__ int hist[132];
    __shared__ int sB, cnts[2];
    int tid = threadIdx.x;
    if (tid < 132) hist[tid] = 0;
    if (tid < 2) cnts[tid] = 0;
    __syncthreads();
    unsigned vals[8];
#pragma unroll
    for (int i = 0; i < 8; i++) {
        unsigned u = row[tid + i * 256];
        vals[i] = u;
        atomicAdd(&hist[u >> 24], 1);
    }
    __syncthreads();
    if (tid == 0) {
        int c = 0, bk = 128;
        while (bk > 0 && c + hist[bk] < KNN) { c += hist[bk]; bk--; }
        sB = bk;
    }
    __syncthreads();
    unsigned Bl = (unsigned)sB;
#pragma unroll
    for (int i = 0; i < 8; i++) {
        int m = tid + i * 256;
        unsigned u = vals[i];
        unsigned bk = u >> 24;
        if (bk > Bl) {
            int slot = atomicAdd(&cnts[0], 1);
            g_idx[r * KNN + slot] = m;
        } else if (bk == Bl) {
            int slot = atomicAdd(&cnts[1], 1);
            cand[slot] = ((unsigned long long)u << 32) | (unsigned)(0xFFFFFFFFu - m);
        }
    }
    __syncthreads();
    if (tid < 32) {
        int base = cnts[0];
        int cnt = cnts[1];
        int need = KNN - base;
        for (int it = 0; it < need; it++) {
            unsigned long long best = 0;
            for (int j = tid; j < cnt; j += 32) {
                unsigned long long k = cand[j];
                if (k > best) best = k;
            }
#pragma unroll
            for (int s = 16; s; s >>= 1) {
                unsigned long long o = __shfl_xor_sync(0xffffffffu, best, s);
                if (o > best) best = o;
            }
            if (tid == 0)
                g_idx[r * KNN + base + it] =
                    (int)(0xFFFFFFFFu - (unsigned)(best & 0xFFFFFFFFull));
            for (int j = tid; j < cnt; j += 32)
                if (cand[j] == best) cand[j] = 0;
            __syncwarp();
        }
    }
}

// ---------------- pack [W1 ; W2-W1] ----------------
__global__ void build_wpq(const float* __restrict__ W, int Cout, int Cin) {
    int i = blockIdx.x * 256 + threadIdx.x;
    if (i >= Cout * Cin) return;
    int o = i / Cin, c = i - o * Cin;
    float w1 = W[(size_t)o * 2 * Cin + c];
    float w2 = W[(size_t)o * 2 * Cin + Cin + c];
    g_Wpq[(size_t)o * Cin + c] = w1;
    g_Wpq[(size_t)(Cout + o) * Cin + c] = w2 - w1;
}

// ---------------- neighbor reduce: partial stats + M = max_k P[nb] + Q ----------------
__global__ void nbr_reduce(int Cout) {
    int o = blockIdx.x, b = blockIdx.y;
    __shared__ float sp[N_PTS];
    __shared__ double rs1[256], rs2[256];
    int tid = threadIdx.x;
    const float* Prow = g_PQ + (size_t)o * NB + b * N_PTS;
    const float* Qrow = g_PQ + (size_t)(Cout + o) * NB + b * N_PTS;
    for (int i = tid; i < N_PTS; i += 256) sp[i] = Prow[i];
    __syncthreads();
    double s1 = 0.0, s2 = 0.0;
    for (int n = tid; n < N_PTS; n += 256) {
        const int* ip = g_idx + (size_t)(b * N_PTS + n) * KNN;
        float mx = -1e30f, su = 0.f, su2 = 0.f;
#pragma unroll
        for (int k = 0; k < KNN; k++) {
            float p = sp[ip[k]];
            mx = fmaxf(mx, p);
            su += p;
            su2 += p * p;
        }
        float q = Qrow[n];
        g_M[(size_t)o * NB + b * N_PTS + n] = mx + q;
        s1 += (double)su + 20.0 * (double)q;
        s2 += (double)su2 + 2.0 * (double)q * (double)su + 20.0 * (double)q * (double)q;
    }
    rs1[tid] = s1;
    rs2[tid] = s2;
    __syncthreads();
    for (int st = 128; st; st >>= 1) {
        if (tid < st) { rs1[tid] += rs1[tid + st]; rs2[tid] += rs2[tid + st]; }
        __syncthreads();
    }
    if (!tid) {
        g_ps[o * 4 + b] = rs1[0];
        g_pq2[o * 4 + b] = rs2[0];
    }
}

__global__ void finalize_bn(const float* __restrict__ gam, const float* __restrict__ bet,
                            int Cout, double cnt, int nparts) {
    int o = blockIdx.x * 256 + threadIdx.x;
    if (o >= Cout) return;
    double s = 0.0, q = 0.0;
    for (int j = 0; j < nparts; j++) {
        s += g_ps[o * nparts + j];
        q += g_pq2[o * nparts + j];
    }
    double m = s / cnt;
    double v = q / cnt - m * m;
    float sc = (float)((double)gam[o] / sqrt(v + 1e-5));
    g_scale[o] = sc;
    g_shift[o] = bet[o] - (float)m * sc;
}

// ---------------- apply BN+LReLU to M -> Ht (pos-major) ----------------
__global__ void apply_bn(int Cout, int dstoff) {
    int bn = blockIdx.x;
    for (int o = threadIdx.x; o < Cout; o += blockDim.x) {
        float v = g_M[(size_t)o * NB + bn] * g_scale[o] + g_shift[o];
        v = v > 0.f ? v : NEG_SLOPE * v;
        g_Ht[(size_t)bn * HCH + dstoff + o] = v;
    }
}

// ---------------- conv5 partial stats ----------------
__global__ void stats_y5() {
    int o = blockIdx.x;
    size_t base = (size_t)o * NB + blockIdx.y * 1024;
    double s = 0.0, q = 0.0;
    for (int i = threadIdx.x; i < 1024; i += 256) {
        double v = (double)g_Y5[base + i];
        s += v;
        q += v * v;
    }
    __shared__ double sh[256];
    int tid = threadIdx.x;
    sh[tid] = s;
    __syncthreads();
    for (int st = 128; st; st >>= 1) {
        if (tid < st) sh[tid] += sh[tid + st];
        __syncthreads();
    }
    double ts = sh[0];
    __syncthreads();
    sh[tid] = q;
    __syncthreads();
    for (int st = 128; st; st >>= 1) {
        if (tid < st) sh[tid] += sh[tid + st];
        __syncthreads();
    }
    if (!tid) {
        g_ps[o * 8 + blockIdx.y] = ts;
        g_pq2[o * 8 + blockIdx.y] = sh[0];
    }
}

// ---------------- conv5 BN + LReLU + max & mean over N -> z ----------------
__global__ void zmaxmean_kernel() {
    int o = blockIdx.x, b = blockIdx.y;
    const float* row = g_Y5 + (size_t)o * NB + (size_t)b * N_PTS;
    float sc = g_scale[o], sh = g_shift[o];
    float mx = -1e30f, sm = 0.f;
    for (int n = threadIdx.x; n < N_PTS; n += 256) {
        float v = row[n] * sc + sh;
        v = v > 0.f ? v : NEG_SLOPE * v;
        mx = fmaxf(mx, v);
        sm += v;
    }
    __shared__ float smx[256];
    __shared__ float ssm[256];
    int tid = threadIdx.x;
    smx[tid] = mx;
    ssm[tid] = sm;
    __syncthreads();
    for (int st = 128; st; st >>= 1) {
        if (tid < st) {
            smx[tid] = fmaxf(smx[tid], smx[tid + st]);
            ssm[tid] += ssm[tid + st];
        }
        __syncthreads();
    }
    if (!tid) {
        g_z[b * 2048 + o] = smx[0];
        g_z[b * 2048 + 1024 + o] = ssm[0] * (1.f / 2048.f);
    }
}

// ---------------- MLP head ----------------
__global__ void head_kernel(const float* __restrict__ lw1, const float* __restrict__ lb1,
                            const float* __restrict__ lw2, const float* __restrict__ lb2,
                            const float* __restrict__ lw3, const float* __restrict__ lb3,
                            int slot, float* __restrict__ out) {
    int b = blockIdx.x, tid = threadIdx.x;
    __shared__ float zs[2048];
    __shared__ float z1[256];
    __shared__ float z2[64];
    for (int i = tid; i < 2048; i += 256) zs[i] = g_z[b * 2048 + i];
    __syncthreads();
    {
        float a = lb1[tid];
        const float* wr = lw1 + (size_t)tid * 2048;
        for (int c = 0; c < 2048; c++) a += wr[c] * zs[c];
        z1[tid] = a;
    }
    __syncthreads();
    if (tid < 64) {
        float a = lb2[tid];
        const float* wr = lw2 + (size_t)tid * 256;
        for (int c = 0; c < 256; c++) a += wr[c] * z1[c];
        z2[tid] = a;
    }
    __syncthreads();
    if (tid < 10) {
        float a = lb3[tid];
        const float* wr = lw3 + (size_t)tid * 64;
        for (int c = 0; c < 64; c++) a += wr[c] * z2[c];
        g_e[slot * 40 + b * 10 + tid] = a;
        out[6404 + slot * 40 + b * 10 + tid] = a;
    }
}

// ---------------- cluster assignment ----------------
__global__ void cluster_kernel(const float* __restrict__ cw, int slot,
                               float* __restrict__ out) {
    int b = blockIdx.x, j = threadIdx.x;
    __shared__ float es[10];
    __shared__ float red[1024];
    if (j < 10) es[j] = g_e[slot * 40 + b * 10 + j];
    __syncthreads();
    float xd = 0.f, qn = 0.f;
    if (j < 800) {
#pragma unroll
        for (int t = 0; t < 10; t++) {
            float d = es[t] - cw[j * 10 + t];
            xd += d * d;
        }
        qn = 1.f / (1.f + xd);
    }
    red[j] = qn;
    __syncthreads();
    for (int st = 512; st; st >>= 1) {
        if (j < st) red[j] += red[j + st];
        __syncthreads();
    }
    float tot = red[0];
    if (j < 800) {
        out[4 + slot * 3200 + b * 800 + j] = qn / tot;
        if (!slot) out[6484 + b * 800 + j] = xd;
    }
}

__global__ void sim_kernel(float* __restrict__ out) {
    int b = threadIdx.x;
    if (b < 4) {
        float s = 0.f;
        for (int j = 0; j < 10; j++) {
            float d = g_e[b * 10 + j] - g_e[40 + b * 10 + j] + 1e-6f;
            s += d * d;
        }
        out[b] = sqrtf(s);
    }
}

// ---------------- host orchestration ----------------
extern "C" void kernel_launch(void* const* d_in, const int* in_sizes, int n_in,
                              void* d_out, int out_size) {
    const float* x1 = (const float*)d_in[0];
    const float* x2 = (const float*)d_in[1];
    const float* Wl[4] = {(const float*)d_in[2], (const float*)d_in[5],
                          (const float*)d_in[8], (const float*)d_in[11]};
    const float* Gl[4] = {(const float*)d_in[3], (const float*)d_in[6],
                          (const float*)d_in[9], (const float*)d_in[12]};
    const float* Bl[4] = {(const float*)d_in[4], (const float*)d_in[7],
                          (const float*)d_in[10], (const float*)d_in[13]};
    const float* w5 = (const float*)d_in[14];
    const float* g5 = (const float*)d_in[15];
    const float* b5 = (const float*)d_in[16];
    const float* lw1 = (const float*)d_in[17];
    const float* lb1 = (const float*)d_in[18];
    const float* lw2 = (const float*)d_in[19];
    const float* lb2 = (const float*)d_in[20];
    const float* lw3 = (const float*)d_in[21];
    const float* lb3 = (const float*)d_in[22];
    const float* cw = (const float*)d_in[23];
    float* out = (float*)d_out;

    const int Cin[4] = {3, 64, 64, 128};
    const int Cout[4] = {64, 64, 128, 256};
    const int choff[4] = {0, 0, 64, 128};
    const int dstoff[4] = {0, 64, 128, 256};

    float* xtp = nullptr;
    float* htp = nullptr;
    float* wpq = nullptr;
    float* pq = nullptr;
    float* y5 = nullptr;
    cudaGetSymbolAddress((void**)&xtp, g_Xt);
    cudaGetSymbolAddress((void**)&htp, g_Ht);
    cudaGetSymbolAddress((void**)&wpq, g_Wpq);
    cudaGetSymbolAddress((void**)&pq, g_PQ);
    cudaGetSymbolAddress((void**)&y5, g_Y5);

    for (int s = 0; s < 2; s++) {
        const float* x = s ? x2 : x1;
        transpose_x<<<NB / 256, 256>>>(x);
        for (int l = 0; l < 4; l++) {
            const float* F = (l == 0) ? xtp : (htp + choff[l]);
            int ldf = (l == 0) ? 4 : HCH;
            int rowLen = (l == 0) ? 4 : Cin[l];
            size_t bstride = (size_t)N_PTS * ldf;
            compute_xx<<<NB / 256, 256>>>(F, ldf, Cin[l]);
            pd_gemm2<<<dim3(16, 16, B_SZ), 256>>>(F, ldf, rowLen, Cin[l], bstride);
            topk_kernel<<<NB, 256>>>();
            build_wpq<<<(Cout[l] * Cin[l] + 255) / 256, 256>>>(Wl[l], Cout[l], Cin[l]);
            sgemm_wn<<<dim3(NB / 128, 2 * Cout[l] / 128), 256>>>(wpq, Cin[l], Cin[l], F,
                                                                 ldf, rowLen, pq, NB);
            nbr_reduce<<<dim3(Cout[l], B_SZ), 256>>>(Cout[l]);
            finalize_bn<<<1, 256>>>(Gl[l], Bl[l], Cout[l], (double)PPOS, 4);
            apply_bn<<<NB, 256>>>(Cout[l], dstoff[l]);
        }
        sgemm_wn<<<dim3(NB / 128, 1024 / 128), 256>>>(w5, HCH, HCH, htp, HCH, HCH, y5,
                                                      NB);
        stats_y5<<<dim3(1024, 8), 256>>>();
        finalize_bn<<<4, 256>>>(g5, b5, 1024, (double)NB, 8);
        zmaxmean_kernel<<<dim3(1024, 4), 256>>>();
        head_kernel<<<4, 256>>>(lw1, lb1, lw2, lb2, lw3, lb3, s, out);
        cluster_kernel<<<4, 1024>>>(cw, s, out);
    }
    sim_kernel<<<1, 32>>>(out);
}

// round 13
// speedup vs baseline: 1.1026x; 1.0993x over previous
#include <cuda_runtime.h>
#include <cuda_bf16.h>
#include <cstdint>
#include <math.h>

#define N_PTS 2048
#define B_SZ 4
#define NB (B_SZ * N_PTS)          // 8192 positions
#define KNN 20
#define PPOS (NB * KNN)            // 163840
#define HCH 512
#define NEG_SLOPE 0.2f

// ---------------- scratch (static device globals) ----------------
__device__ unsigned g_pd[B_SZ * N_PTS * N_PTS];  // 64 MB, ordered u32 keys
__device__ float  g_xx[NB];
__device__ int    g_idx[NB * KNN];
__device__ float  g_Xt[NB * 4];                 // pos-major x, padded stride 4
__device__ float  g_Ht[NB * HCH];               // pos-major features [bn][512]
__device__ float  g_Wpq[512 * 128];             // packed [W1 ; W2-W1]
__device__ float  g_PQ[512 * NB + 8];           // P rows then Q rows, o-major
__device__ float  g_M[256 * NB];                // maxP + Q per (o, bn)
__device__ float  g_Y5[1024 * NB];              // conv5 pre-BN output
__device__ double g_ps[1024 * 8], g_pq2[1024 * 8];  // BN partial sums (o, part)
__device__ float  g_scale[1024], g_shift[1024];
__device__ float  g_z[B_SZ * 2048];
__device__ float  g_e[2 * B_SZ * 10];
// bf16 split operands for tensor-core conv5
__device__ __nv_bfloat16 g_Wh[1024 * HCH], g_Wl[1024 * HCH];
__device__ __nv_bfloat16 g_Hh[NB * HCH], g_Hl[NB * HCH];

__device__ __forceinline__ unsigned fkey(float v) {
    unsigned u = __float_as_uint(v);
    return ((int)u < 0) ? ~u : (u | 0x80000000u);
}
__device__ __forceinline__ uint32_t smem_to_u32(const void* p) {
    uint32_t a;
    asm("{ .reg .u64 t; cvta.to.shared.u64 t, %1; cvt.u32.u64 %0, t; }" : "=r"(a)
        : "l"(p));
    return a;
}

// ---------------- build pos-major x with zero pad ----------------
__global__ void transpose_x(const float* __restrict__ x) {
    int i = blockIdx.x * 256 + threadIdx.x;
    if (i >= NB) return;
    int b = i >> 11, n = i & 2047;
    float4 v;
    v.x = x[(b * 3 + 0) * N_PTS + n];
    v.y = x[(b * 3 + 1) * N_PTS + n];
    v.z = x[(b * 3 + 2) * N_PTS + n];
    v.w = 0.f;
    *(float4*)&g_Xt[i * 4] = v;
}

// ---------------- xx[bn] = sum_c F[bn][c]^2 ----------------
__global__ void compute_xx(const float* __restrict__ F, int ldf, int K) {
    int i = blockIdx.x * 256 + threadIdx.x;
    if (i >= NB) return;
    const float* row = F + (size_t)i * ldf;
    float s = 0.f;
    for (int c = 0; c < K; c++) { float v = row[c]; s += v * v; }
    g_xx[i] = s;
}

// ---------------- pd GEMM: writes ordered u32 keys ----------------
__global__ __launch_bounds__(256, 2) void pd_gemm2(const float* __restrict__ F, int ldf,
                                                   int rowLen, int K, size_t bstride) {
    __shared__ float As[2][16][132];
    __shared__ float Bs[2][16][132];
    int tid = threadIdx.x, tx = tid & 15, ty = tid >> 4;
    int n0 = blockIdx.y * 128, m0 = blockIdx.x * 128;
    int b = blockIdx.z;
    const float* Ab = F + (size_t)b * bstride + (size_t)n0 * ldf;
    const float* Bb = F + (size_t)b * bstride + (size_t)m0 * ldf;
    int k4 = (tid & 3) * 4, rowq = tid >> 2;
    int KIT = (K + 15) >> 4;
    float acc[8][8] = {};
    {
#pragma unroll
        for (int r = 0; r < 2; r++) {
            int rw = rowq + r * 64;
            float4 va = make_float4(0, 0, 0, 0), vb = make_float4(0, 0, 0, 0);
            if (k4 < rowLen) {
                va = *(const float4*)&Ab[(size_t)rw * ldf + k4];
                vb = *(const float4*)&Bb[(size_t)rw * ldf + k4];
            }
            As[0][k4 + 0][rw] = va.x; As[0][k4 + 1][rw] = va.y;
            As[0][k4 + 2][rw] = va.z; As[0][k4 + 3][rw] = va.w;
            Bs[0][k4 + 0][rw] = vb.x; Bs[0][k4 + 1][rw] = vb.y;
            Bs[0][k4 + 2][rw] = vb.z; Bs[0][k4 + 3][rw] = vb.w;
        }
    }
    __syncthreads();
    int buf = 0;
    for (int it = 0; it < KIT; ++it) {
        float4 ra[2], rb[2];
        bool more = (it + 1 < KIT);
        if (more) {
            int k0 = (it + 1) << 4;
#pragma unroll
            for (int r = 0; r < 2; r++) {
                int rw = rowq + r * 64;
                ra[r] = make_float4(0, 0, 0, 0);
                rb[r] = make_float4(0, 0, 0, 0);
                if (k0 + k4 < rowLen) {
                    ra[r] = *(const float4*)&Ab[(size_t)rw * ldf + k0 + k4];
                    rb[r] = *(const float4*)&Bb[(size_t)rw * ldf + k0 + k4];
                }
            }
        }
#pragma unroll
        for (int k = 0; k < 16; k++) {
            float4 a0 = *(const float4*)&As[buf][k][ty * 4];
            float4 a1 = *(const float4*)&As[buf][k][64 + ty * 4];
            float4 b0 = *(const float4*)&Bs[buf][k][tx * 4];
            float4 b1 = *(const float4*)&Bs[buf][k][64 + tx * 4];
            float av[8] = {a0.x, a0.y, a0.z, a0.w, a1.x, a1.y, a1.z, a1.w};
            float bv[8] = {b0.x, b0.y, b0.z, b0.w, b1.x, b1.y, b1.z, b1.w};
#pragma unroll
            for (int i = 0; i < 8; i++)
#pragma unroll
                for (int j = 0; j < 8; j++) acc[i][j] += av[i] * bv[j];
        }
        if (more) {
            int nb2 = buf ^ 1;
#pragma unroll
            for (int r = 0; r < 2; r++) {
                int rw = rowq + r * 64;
                As[nb2][k4 + 0][rw] = ra[r].x; As[nb2][k4 + 1][rw] = ra[r].y;
                As[nb2][k4 + 2][rw] = ra[r].z; As[nb2][k4 + 3][rw] = ra[r].w;
                Bs[nb2][k4 + 0][rw] = rb[r].x; Bs[nb2][k4 + 1][rw] = rb[r].y;
                Bs[nb2][k4 + 2][rw] = rb[r].z; Bs[nb2][k4 + 3][rw] = rb[r].w;
            }
            __syncthreads();
            buf = nb2;
        }
    }
    int mA = m0 + tx * 4, mB = m0 + 64 + tx * 4;
    float xmA[4], xmB[4];
#pragma unroll
    for (int j = 0; j < 4; j++) {
        xmA[j] = g_xx[b * N_PTS + mA + j];
        xmB[j] = g_xx[b * N_PTS + mB + j];
    }
#pragma unroll
    for (int i = 0; i < 8; i++) {
        int n = n0 + (i < 4 ? ty * 4 + i : 64 + ty * 4 + (i - 4));
        float xn = g_xx[b * N_PTS + n];
        uint4 o0, o1;
        o0.x = fkey(2.f * acc[i][0] - xn - xmA[0]);
        o0.y = fkey(2.f * acc[i][1] - xn - xmA[1]);
        o0.z = fkey(2.f * acc[i][2] - xn - xmA[2]);
        o0.w = fkey(2.f * acc[i][3] - xn - xmA[3]);
        o1.x = fkey(2.f * acc[i][4] - xn - xmB[0]);
        o1.y = fkey(2.f * acc[i][5] - xn - xmB[1]);
        o1.z = fkey(2.f * acc[i][6] - xn - xmB[2]);
        o1.w = fkey(2.f * acc[i][7] - xn - xmB[3]);
        size_t base = (size_t)b * N_PTS * N_PTS + (size_t)n * N_PTS;
        *(uint4*)&g_pd[base + mA] = o0;
        *(uint4*)&g_pd[base + mB] = o1;
    }
}

// ---------------- generic GEMM (FFMA) for the small PQ gemms ----------------
__global__ __launch_bounds__(256, 2) void sgemm_wn(const float* __restrict__ A, int lda,
                                                   int K, const float* __restrict__ B,
                                                   int ldb, int rowLenB,
                                                   float* __restrict__ C, int ldc) {
    __shared__ float As[2][16][132];
    __shared__ float Bs[2][16][132];
    int tid = threadIdx.x, tx = tid & 15, ty = tid >> 4;
    int n0 = blockIdx.x * 128, m0 = blockIdx.y * 128;
    const float* Ab = A + (size_t)m0 * lda;
    const float* Bb = B + (size_t)n0 * ldb;
    int k4 = (tid & 3) * 4, rowq = tid >> 2;
    int KIT = (K + 15) >> 4;
    float acc[8][8] = {};
    {
#pragma unroll
        for (int r = 0; r < 8; r++) {
            int m = tx + r * 16;
            As[0][ty][m] = (ty < K) ? Ab[(size_t)m * lda + ty] : 0.f;
        }
#pragma unroll
        for (int r = 0; r < 2; r++) {
            int rw = rowq + r * 64;
            float4 v = make_float4(0, 0, 0, 0);
            if (k4 < rowLenB) v = *(const float4*)&Bb[(size_t)rw * ldb + k4];
            Bs[0][k4 + 0][rw] = v.x; Bs[0][k4 + 1][rw] = v.y;
            Bs[0][k4 + 2][rw] = v.z; Bs[0][k4 + 3][rw] = v.w;
        }
    }
    __syncthreads();
    int buf = 0;
    for (int it = 0; it < KIT; ++it) {
        float ra[8];
        float4 rb[2];
        bool more = (it + 1 < KIT);
        if (more) {
            int k0 = (it + 1) << 4;
#pragma unroll
            for (int r = 0; r < 8; r++) {
                int m = tx + r * 16;
                ra[r] = (k0 + ty < K) ? Ab[(size_t)m * lda + k0 + ty] : 0.f;
            }
#pragma unroll
            for (int r = 0; r < 2; r++) {
                int rw = rowq + r * 64;
                rb[r] = make_float4(0, 0, 0, 0);
                if (k0 + k4 < rowLenB) rb[r] = *(const float4*)&Bb[(size_t)rw * ldb + k0 + k4];
            }
        }
#pragma unroll
        for (int k = 0; k < 16; k++) {
            float4 a0 = *(const float4*)&As[buf][k][ty * 4];
            float4 a1 = *(const float4*)&As[buf][k][64 + ty * 4];
            float4 b0 = *(const float4*)&Bs[buf][k][tx * 4];
            float4 b1 = *(const float4*)&Bs[buf][k][64 + tx * 4];
            float av[8] = {a0.x, a0.y, a0.z, a0.w, a1.x, a1.y, a1.z, a1.w};
            float bv[8] = {b0.x, b0.y, b0.z, b0.w, b1.x, b1.y, b1.z, b1.w};
#pragma unroll
            for (int i = 0; i < 8; i++)
#pragma unroll
                for (int j = 0; j < 8; j++) acc[i][j] += av[i] * bv[j];
        }
        if (more) {
            int nb2 = buf ^ 1;
#pragma unroll
            for (int r = 0; r < 8; r++) As[nb2][ty][tx + r * 16] = ra[r];
#pragma unroll
            for (int r = 0; r < 2; r++) {
                int rw = rowq + r * 64;
                Bs[nb2][k4 + 0][rw] = rb[r].x; Bs[nb2][k4 + 1][rw] = rb[r].y;
                Bs[nb2][k4 + 2][rw] = rb[r].z; Bs[nb2][k4 + 3][rw] = rb[r].w;
            }
            __syncthreads();
            buf = nb2;
        }
    }
#pragma unroll
    for (int i = 0; i < 8; i++) {
        int m = m0 + (i < 4 ? ty * 4 + i : 64 + ty * 4 + (i - 4));
        float4 v0 = make_float4(acc[i][0], acc[i][1], acc[i][2], acc[i][3]);
        float4 v1 = make_float4(acc[i][4], acc[i][5], acc[i][6], acc[i][7]);
        *(float4*)&C[(size_t)m * ldc + n0 + tx * 4] = v0;
        *(float4*)&C[(size_t)m * ldc + n0 + 64 + tx * 4] = v1;
    }
}

// ---------------- bf16 split helpers for conv5 ----------------
__global__ void split_w5(const float* __restrict__ w) {
    int i = blockIdx.x * 256 + threadIdx.x;
    if (i >= 1024 * HCH) return;
    float v = w[i];
    __nv_bfloat16 h = __float2bfloat16(v);
    g_Wh[i] = h;
    g_Wl[i] = __float2bfloat16(v - __bfloat162float(h));
}
__global__ void split_h() {
    int i = blockIdx.x * 256 + threadIdx.x;
    if (i >= NB * HCH) return;
    float v = g_Ht[i];
    __nv_bfloat16 h = __float2bfloat16(v);
    g_Hh[i] = h;
    g_Hl[i] = __float2bfloat16(v - __bfloat162float(h));
}

// ---------------- conv5 via mma.sync bf16 (sm_80+ path, works on plain sm_103) ----
// Y5[o, pos] = sum_c W[o,c]*H[pos,c] with W=Wh+Wl, H=Hh+Hl:
// three terms Wh*Hh + Wh*Hl + Wl*Hh, fp32 accumulators.
// CTA tile 128(o) x 128(pos); 8 warps in 2x4; warp tile 64x32 via m16n8k16.
__global__ __launch_bounds__(256) void conv5_mma(float* __restrict__ C) {
    __shared__ __nv_bfloat16 As[128][40];  // stride 40 elems = 80B (conflict-free ldmatrix)
    __shared__ __nv_bfloat16 Bs[128][40];
    int tid = threadIdx.x;
    int warp = tid >> 5, lane = tid & 31;
    int n0 = blockIdx.x * 128, m0 = blockIdx.y * 128;
    int wm = warp >> 2, wn = warp & 3;  // warp covers rows wm*64.., cols wn*32..
    float acc[4][4][4];
#pragma unroll
    for (int i = 0; i < 4; i++)
#pragma unroll
        for (int j = 0; j < 4; j++)
#pragma unroll
            for (int k = 0; k < 4; k++) acc[i][j][k] = 0.f;
    uint32_t aBase = smem_to_u32(&As[0][0]);
    uint32_t bBase = smem_to_u32(&Bs[0][0]);

    for (int it = 0; it < 48; it++) {
        int t = it >> 4, k0 = (it & 15) << 5;
        const __nv_bfloat16* Ag = (t == 2) ? g_Wl : g_Wh;
        const __nv_bfloat16* Bg = (t == 1) ? g_Hl : g_Hh;
#pragma unroll
        for (int i = 0; i < 2; i++) {
            int blk = i * 256 + tid;  // 512 16B-blocks per tile
            int row = blk >> 2, cb = blk & 3;
            *(uint4*)((char*)&As[row][0] + cb * 16) =
                *(const uint4*)&Ag[(size_t)(m0 + row) * HCH + k0 + cb * 8];
            *(uint4*)((char*)&Bs[row][0] + cb * 16) =
                *(const uint4*)&Bg[(size_t)(n0 + row) * HCH + k0 + cb * 8];
        }
        __syncthreads();
#pragma unroll
        for (int kk = 0; kk < 2; kk++) {
            uint32_t a[4][4];
#pragma unroll
            for (int mf = 0; mf < 4; mf++) {
                // x4: matrices {m0-7,k0-7},{m8-15,k0-7},{m0-7,k8-15},{m8-15,k8-15}
                int row = wm * 64 + mf * 16 + (lane & 7) + ((lane >> 3) & 1) * 8;
                int col = kk * 16 + (lane >> 4) * 8;
                uint32_t addr = aBase + (uint32_t)(row * 80 + col * 2);
                asm volatile(
                    "ldmatrix.sync.aligned.m8n8.x4.shared.b16 {%0,%1,%2,%3}, [%4];"
                    : "=r"(a[mf][0]), "=r"(a[mf][1]), "=r"(a[mf][2]), "=r"(a[mf][3])
                    : "r"(addr));
            }
            uint32_t b[4][2];
#pragma unroll
            for (int np = 0; np < 2; np++) {
                // x4: {n0-7,k0-7},{n0-7,k8-15},{n8-15,k0-7},{n8-15,k8-15}
                int row = wn * 32 + np * 16 + (lane & 7) + ((lane >> 4) & 1) * 8;
                int col = kk * 16 + ((lane >> 3) & 1) * 8;
                uint32_t addr = bBase + (uint32_t)(row * 80 + col * 2);
                asm volatile(
                    "ldmatrix.sync.aligned.m8n8.x4.shared.b16 {%0,%1,%2,%3}, [%4];"
                    : "=r"(b[np * 2][0]), "=r"(b[np * 2][1]), "=r"(b[np * 2 + 1][0]),
                      "=r"(b[np * 2 + 1][1])
                    : "r"(addr));
            }
#pragma unroll
            for (int mf = 0; mf < 4; mf++)
#pragma unroll
                for (int nf = 0; nf < 4; nf++)
                    asm volatile(
                        "mma.sync.aligned.m16n8k16.row.col.f32.bf16.bf16.f32 "
                        "{%0,%1,%2,%3}, {%4,%5,%6,%7}, {%8,%9}, {%0,%1,%2,%3};"
                        : "+f"(acc[mf][nf][0]), "+f"(acc[mf][nf][1]),
                          "+f"(acc[mf][nf][2]), "+f"(acc[mf][nf][3])
                        : "r"(a[mf][0]), "r"(a[mf][1]), "r"(a[mf][2]), "r"(a[mf][3]),
                          "r"(b[nf][0]), "r"(b[nf][1]));
        }
        __syncthreads();
    }
    int g = lane >> 2, tq = lane & 3;
#pragma unroll
    for (int mf = 0; mf < 4; mf++)
#pragma unroll
        for (int nf = 0; nf < 4; nf++) {
            int o0 = m0 + wm * 64 + mf * 16 + g;
            int p = n0 + wn * 32 + nf * 8 + tq * 2;
            *(float2*)&C[(size_t)o0 * NB + p] =
                make_float2(acc[mf][nf][0], acc[mf][nf][1]);
            *(float2*)&C[(size_t)(o0 + 8) * NB + p] =
                make_float2(acc[mf][nf][2], acc[mf][nf][3]);
        }
}

// ---------------- top-20 per row via bucket select ----------------
__global__ __launch_bounds__(256) void topk_kernel() {
    int r = blockIdx.x;
    const unsigned* row = g_pd + (size_t)r * N_PTS;
    __shared__ unsigned long long cand[N_PTS];
    __shared__ int hist[132];
    __shared__ int sB, cnts[2];
    int tid = threadIdx.x;
    if (tid < 132) hist[tid] = 0;
    if (tid < 2) cnts[tid] = 0;
    __syncthreads();
    unsigned vals[8];
#pragma unroll
    for (int i = 0; i < 8; i++) {
        unsigned u = row[tid + i * 256];
        vals[i] = u;
        atomicAdd(&hist[u >> 24], 1);
    }
    __syncthreads();
    if (tid == 0) {
        int c = 0, bk = 128;
        while (bk > 0 && c + hist[bk] < KNN) { c += hist[bk]; bk--; }
        sB = bk;
    }
    __syncthreads();
    unsigned Bl = (unsigned)sB;
#pragma unroll
    for (int i = 0; i < 8; i++) {
        int m = tid + i * 256;
        unsigned u = vals[i];
        unsigned bk = u >> 24;
        if (bk > Bl) {
            int slot = atomicAdd(&cnts[0], 1);
            g_idx[r * KNN + slot] = m;
        } else if (bk == Bl) {
            int slot = atomicAdd(&cnts[1], 1);
            cand[slot] = ((unsigned long long)u << 32) | (unsigned)(0xFFFFFFFFu - m);
        }
    }
    __syncthreads();
    if (tid < 32) {
        int base = cnts[0];
        int cnt = cnts[1];
        int need = KNN - base;
        for (int it = 0; it < need; it++) {
            unsigned long long best = 0;
            for (int j = tid; j < cnt; j += 32) {
                unsigned long long k = cand[j];
                if (k > best) best = k;
            }
#pragma unroll
            for (int s = 16; s; s >>= 1) {
                unsigned long long o = __shfl_xor_sync(0xffffffffu, best, s);
                if (o > best) best = o;
            }
            if (tid == 0)
                g_idx[r * KNN + base + it] =
                    (int)(0xFFFFFFFFu - (unsigned)(best & 0xFFFFFFFFull));
            for (int j = tid; j < cnt; j += 32)
                if (cand[j] == best) cand[j] = 0;
            __syncwarp();
        }
    }
}

// ---------------- pack [W1 ; W2-W1] ----------------
__global__ void build_wpq(const float* __restrict__ W, int Cout, int Cin) {
    int i = blockIdx.x * 256 + threadIdx.x;
    if (i >= Cout * Cin) return;
    int o = i / Cin, c = i - o * Cin;
    float w1 = W[(size_t)o * 2 * Cin + c];
    float w2 = W[(size_t)o * 2 * Cin + Cin + c];
    g_Wpq[(size_t)o * Cin + c] = w1;
    g_Wpq[(size_t)(Cout + o) * Cin + c] = w2 - w1;
}

// ---------------- neighbor reduce: partial stats + M = max_k P[nb] + Q ----------------
__global__ void nbr_reduce(int Cout) {
    int o = blockIdx.x, b = blockIdx.y;
    __shared__ float sp[N_PTS];
    __shared__ double rs1[256], rs2[256];
    int tid = threadIdx.x;
    const float* Prow = g_PQ + (size_t)o * NB + b * N_PTS;
    const float* Qrow = g_PQ + (size_t)(Cout + o) * NB + b * N_PTS;
    for (int i = tid; i < N_PTS; i += 256) sp[i] = Prow[i];
    __syncthreads();
    double s1 = 0.0, s2 = 0.0;
    for (int n = tid; n < N_PTS; n += 256) {
        const int* ip = g_idx + (size_t)(b * N_PTS + n) * KNN;
        float mx = -1e30f, su = 0.f, su2 = 0.f;
#pragma unroll
        for (int k = 0; k < KNN; k++) {
            float p = sp[ip[k]];
            mx = fmaxf(mx, p);
            su += p;
            su2 += p * p;
        }
        float q = Qrow[n];
        g_M[(size_t)o * NB + b * N_PTS + n] = mx + q;
        s1 += (double)su + 20.0 * (double)q;
        s2 += (double)su2 + 2.0 * (double)q * (double)su + 20.0 * (double)q * (double)q;
    }
    rs1[tid] = s1;
    rs2[tid] = s2;
    __syncthreads();
    for (int st = 128; st; st >>= 1) {
        if (tid < st) { rs1[tid] += rs1[tid + st]; rs2[tid] += rs2[tid + st]; }
        __syncthreads();
    }
    if (!tid) {
        g_ps[o * 4 + b] = rs1[0];
        g_pq2[o * 4 + b] = rs2[0];
    }
}

__global__ void finalize_bn(const float* __restrict__ gam, const float* __restrict__ bet,
                            int Cout, double cnt, int nparts) {
    int o = blockIdx.x * 256 + threadIdx.x;
    if (o >= Cout) return;
    double s = 0.0, q = 0.0;
    for (int j = 0; j < nparts; j++) {
        s += g_ps[o * nparts + j];
        q += g_pq2[o * nparts + j];
    }
    double m = s / cnt;
    double v = q / cnt - m * m;
    float sc = (float)((double)gam[o] / sqrt(v + 1e-5));
    g_scale[o] = sc;
    g_shift[o] = bet[o] - (float)m * sc;
}

// ---------------- apply BN+LReLU to M -> Ht (pos-major) ----------------
__global__ void apply_bn(int Cout, int dstoff) {
    int bn = blockIdx.x;
    for (int o = threadIdx.x; o < Cout; o += blockDim.x) {
        float v = g_M[(size_t)o * NB + bn] * g_scale[o] + g_shift[o];
        v = v > 0.f ? v : NEG_SLOPE * v;
        g_Ht[(size_t)bn * HCH + dstoff + o] = v;
    }
}

// ---------------- conv5 partial stats ----------------
__global__ void stats_y5() {
    int o = blockIdx.x;
    size_t base = (size_t)o * NB + blockIdx.y * 1024;
    double s = 0.0, q = 0.0;
    for (int i = threadIdx.x; i < 1024; i += 256) {
        double v = (double)g_Y5[base + i];
        s += v;
        q += v * v;
    }
    __shared__ double sh[256];
    int tid = threadIdx.x;
    sh[tid] = s;
    __syncthreads();
    for (int st = 128; st; st >>= 1) {
        if (tid < st) sh[tid] += sh[tid + st];
        __syncthreads();
    }
    double ts = sh[0];
    __syncthreads();
    sh[tid] = q;
    __syncthreads();
    for (int st = 128; st; st >>= 1) {
        if (tid < st) sh[tid] += sh[tid + st];
        __syncthreads();
    }
    if (!tid) {
        g_ps[o * 8 + blockIdx.y] = ts;
        g_pq2[o * 8 + blockIdx.y] = sh[0];
    }
}

// ---------------- conv5 BN + LReLU + max & mean over N -> z ----------------
__global__ void zmaxmean_kernel() {
    int o = blockIdx.x, b = blockIdx.y;
    const float* row = g_Y5 + (size_t)o * NB + (size_t)b * N_PTS;
    float sc = g_scale[o], sh = g_shift[o];
    float mx = -1e30f, sm = 0.f;
    for (int n = threadIdx.x; n < N_PTS; n += 256) {
        float v = row[n] * sc + sh;
        v = v > 0.f ? v : NEG_SLOPE * v;
        mx = fmaxf(mx, v);
        sm += v;
    }
    __shared__ float smx[256];
    __shared__ float ssm[256];
    int tid = threadIdx.x;
    smx[tid] = mx;
    ssm[tid] = sm;
    __syncthreads();
    for (int st = 128; st; st >>= 1) {
        if (tid < st) {
            smx[tid] = fmaxf(smx[tid], smx[tid + st]);
            ssm[tid] += ssm[tid + st];
        }
        __syncthreads();
    }
    if (!tid) {
        g_z[b * 2048 + o] = smx[0];
        g_z[b * 2048 + 1024 + o] = ssm[0] * (1.f / 2048.f);
    }
}

// ---------------- MLP head ----------------
__global__ void head_kernel(const float* __restrict__ lw1, const float* __restrict__ lb1,
                            const float* __restrict__ lw2, const float* __restrict__ lb2,
                            const float* __restrict__ lw3, const float* __restrict__ lb3,
                            int slot, float* __restrict__ out) {
    int b = blockIdx.x, tid = threadIdx.x;
    __shared__ float zs[2048];
    __shared__ float z1[256];
    __shared__ float z2[64];
    for (int i = tid; i < 2048; i += 256) zs[i] = g_z[b * 2048 + i];
    __syncthreads();
    {
        float a = lb1[tid];
        const float* wr = lw1 + (size_t)tid * 2048;
        for (int c = 0; c < 2048; c++) a += wr[c] * zs[c];
        z1[tid] = a;
    }
    __syncthreads();
    if (tid < 64) {
        float a = lb2[tid];
        const float* wr = lw2 + (size_t)tid * 256;
        for (int c = 0; c < 256; c++) a += wr[c] * z1[c];
        z2[tid] = a;
    }
    __syncthreads();
    if (tid < 10) {
        float a = lb3[tid];
        const float* wr = lw3 + (size_t)tid * 64;
        for (int c = 0; c < 64; c++) a += wr[c] * z2[c];
        g_e[slot * 40 + b * 10 + tid] = a;
        out[6404 + slot * 40 + b * 10 + tid] = a;
    }
}

// ---------------- cluster assignment ----------------
__global__ void cluster_kernel(const float* __restrict__ cw, int slot,
                               float* __restrict__ out) {
    int b = blockIdx.x, j = threadIdx.x;
    __shared__ float es[10];
    __shared__ float red[1024];
    if (j < 10) es[j] = g_e[slot * 40 + b * 10 + j];
    __syncthreads();
    float xd = 0.f, qn = 0.f;
    if (j < 800) {
#pragma unroll
        for (int t = 0; t < 10; t++) {
            float d = es[t] - cw[j * 10 + t];
            xd += d * d;
        }
        qn = 1.f / (1.f + xd);
    }
    red[j] = qn;
    __syncthreads();
    for (int st = 512; st; st >>= 1) {
        if (j < st) red[j] += red[j + st];
        __syncthreads();
    }
    float tot = red[0];
    if (j < 800) {
        out[4 + slot * 3200 + b * 800 + j] = qn / tot;
        if (!slot) out[6484 + b * 800 + j] = xd;
    }
}

__global__ void sim_kernel(float* __restrict__ out) {
    int b = threadIdx.x;
    if (b < 4) {
        float s = 0.f;
        for (int j = 0; j < 10; j++) {
            float d = g_e[b * 10 + j] - g_e[40 + b * 10 + j] + 1e-6f;
            s += d * d;
        }
        out[b] = sqrtf(s);
    }
}

// ---------------- host orchestration ----------------
extern "C" void kernel_launch(void* const* d_in, const int* in_sizes, int n_in,
                              void* d_out, int out_size) {
    const float* x1 = (const float*)d_in[0];
    const float* x2 = (const float*)d_in[1];
    const float* Wl[4] = {(const float*)d_in[2], (const float*)d_in[5],
                          (const float*)d_in[8], (const float*)d_in[11]};
    const float* Gl[4] = {(const float*)d_in[3], (const float*)d_in[6],
                          (const float*)d_in[9], (const float*)d_in[12]};
    const float* Bl[4] = {(const float*)d_in[4], (const float*)d_in[7],
                          (const float*)d_in[10], (const float*)d_in[13]};
    const float* w5 = (const float*)d_in[14];
    const float* g5 = (const float*)d_in[15];
    const float* b5 = (const float*)d_in[16];
    const float* lw1 = (const float*)d_in[17];
    const float* lb1 = (const float*)d_in[18];
    const float* lw2 = (const float*)d_in[19];
    const float* lb2 = (const float*)d_in[20];
    const float* lw3 = (const float*)d_in[21];
    const float* lb3 = (const float*)d_in[22];
    const float* cw = (const float*)d_in[23];
    float* out = (float*)d_out;

    const int Cin[4] = {3, 64, 64, 128};
    const int Cout[4] = {64, 64, 128, 256};
    const int choff[4] = {0, 0, 64, 128};
    const int dstoff[4] = {0, 64, 128, 256};

    float* xtp = nullptr;
    float* htp = nullptr;
    float* wpq = nullptr;
    float* pq = nullptr;
    float* y5 = nullptr;
    cudaGetSymbolAddress((void**)&xtp, g_Xt);
    cudaGetSymbolAddress((void**)&htp, g_Ht);
    cudaGetSymbolAddress((void**)&wpq, g_Wpq);
    cudaGetSymbolAddress((void**)&pq, g_PQ);
    cudaGetSymbolAddress((void**)&y5, g_Y5);

    split_w5<<<(1024 * HCH + 255) / 256, 256>>>(w5);

    for (int s = 0; s < 2; s++) {
        const float* x = s ? x2 : x1;
        transpose_x<<<NB / 256, 256>>>(x);
        for (int l = 0; l < 4; l++) {
            const float* F = (l == 0) ? xtp : (htp + choff[l]);
            int ldf = (l == 0) ? 4 : HCH;
            int rowLen = (l == 0) ? 4 : Cin[l];
            size_t bstride = (size_t)N_PTS * ldf;
            compute_xx<<<NB / 256, 256>>>(F, ldf, Cin[l]);
            pd_gemm2<<<dim3(16, 16, B_SZ), 256>>>(F, ldf, rowLen, Cin[l], bstride);
            topk_kernel<<<NB, 256>>>();
            build_wpq<<<(Cout[l] * Cin[l] + 255) / 256, 256>>>(Wl[l], Cout[l], Cin[l]);
            sgemm_wn<<<dim3(NB / 128, 2 * Cout[l] / 128), 256>>>(wpq, Cin[l], Cin[l], F,
                                                                 ldf, rowLen, pq, NB);
            nbr_reduce<<<dim3(Cout[l], B_SZ), 256>>>(Cout[l]);
            finalize_bn<<<1, 256>>>(Gl[l], Bl[l], Cout[l], (double)PPOS, 4);
            apply_bn<<<NB, 256>>>(Cout[l], dstoff[l]);
        }
        split_h<<<(NB * HCH + 255) / 256, 256>>>();
        conv5_mma<<<dim3(NB / 128, 1024 / 128), 256>>>(y5);
        stats_y5<<<dim3(1024, 8), 256>>>();
        finalize_bn<<<4, 256>>>(g5, b5, 1024, (double)NB, 8);
        zmaxmean_kernel<<<dim3(1024, 4), 256>>>();
        head_kernel<<<4, 256>>>(lw1, lb1, lw2, lb2, lw3, lb3, s, out);
        cluster_kernel<<<4, 1024>>>(cw, s, out);
    }
    sim_kernel<<<1, 32>>>(out);
}

// round 14
// speedup vs baseline: 1.2584x; 1.1413x over previous
#include <cuda_runtime.h>
#include <cuda_bf16.h>
#include <cstdint>
#include <math.h>

#define N_PTS 2048
#define B2 8                        // both inputs batched: 2 slots x 4
#define NB2 (B2 * N_PTS)            // 16384 positions
#define KNN 20
#define PPOS (4 * N_PTS * KNN)      // per-slot BN count: 163840
#define HCH 512
#define NEG_SLOPE 0.2f

// ---------------- scratch (static device globals) ----------------
__device__ unsigned g_pd[B2 * N_PTS * N_PTS];   // 128 MB, ordered u32 keys
__device__ float  g_xx[NB2];
__device__ int    g_idx[NB2 * KNN];
__device__ float  g_Xt[NB2 * 4];                // pos-major x, padded stride 4
__device__ float  g_Ht[NB2 * HCH];              // pos-major features [bn][512]
__device__ float  g_Wpq[512 * 128];             // packed [W1 ; W2-W1]
__device__ float  g_PQ[512 * NB2 + 8];          // P rows then Q rows, o-major
__device__ float  g_M[256 * NB2];               // maxP + Q per (o, bn)
__device__ float  g_Y5[1024 * NB2];             // conv5 pre-BN output
__device__ double g_ps[1024 * 16], g_pq2[1024 * 16];  // BN partial sums
__device__ float  g_scale[2048], g_shift[2048]; // two slots x 1024
__device__ float  g_z[B2 * 2048];
__device__ float  g_e[2 * 4 * 10];
// bf16 split operands for tensor-core conv5
__device__ __nv_bfloat16 g_Wh[1024 * HCH], g_Wl[1024 * HCH];
__device__ __nv_bfloat16 g_Hh[NB2 * HCH], g_Hl[NB2 * HCH];

__device__ __forceinline__ unsigned fkey(float v) {
    unsigned u = __float_as_uint(v);
    return ((int)u < 0) ? ~u : (u | 0x80000000u);
}
__device__ __forceinline__ uint32_t smem_to_u32(const void* p) {
    uint32_t a;
    asm("{ .reg .u64 t; cvta.to.shared.u64 t, %1; cvt.u32.u64 %0, t; }" : "=r"(a)
        : "l"(p));
    return a;
}

// ---------------- build pos-major x (both inputs) with zero pad ----------------
__global__ void transpose_x(const float* __restrict__ x1, const float* __restrict__ x2) {
    int i = blockIdx.x * 256 + threadIdx.x;
    if (i >= NB2) return;
    int b = i >> 11, n = i & 2047;
    const float* x = (b < 4) ? x1 : x2;
    int bb = b & 3;
    float4 v;
    v.x = x[(bb * 3 + 0) * N_PTS + n];
    v.y = x[(bb * 3 + 1) * N_PTS + n];
    v.z = x[(bb * 3 + 2) * N_PTS + n];
    v.w = 0.f;
    *(float4*)&g_Xt[i * 4] = v;
}

// ---------------- xx[bn] = sum_c F[bn][c]^2 ----------------
__global__ void compute_xx(const float* __restrict__ F, int ldf, int K) {
    int i = blockIdx.x * 256 + threadIdx.x;
    if (i >= NB2) return;
    const float* row = F + (size_t)i * ldf;
    float s = 0.f;
    for (int c = 0; c < K; c++) { float v = row[c]; s += v * v; }
    g_xx[i] = s;
}

// ---------------- pd GEMM: writes ordered u32 keys ----------------
__global__ __launch_bounds__(256, 2) void pd_gemm2(const float* __restrict__ F, int ldf,
                                                   int rowLen, int K, size_t bstride) {
    __shared__ float As[2][16][132];
    __shared__ float Bs[2][16][132];
    int tid = threadIdx.x, tx = tid & 15, ty = tid >> 4;
    int n0 = blockIdx.y * 128, m0 = blockIdx.x * 128;
    int b = blockIdx.z;
    const float* Ab = F + (size_t)b * bstride + (size_t)n0 * ldf;
    const float* Bb = F + (size_t)b * bstride + (size_t)m0 * ldf;
    int k4 = (tid & 3) * 4, rowq = tid >> 2;
    int KIT = (K + 15) >> 4;
    float acc[8][8] = {};
    {
#pragma unroll
        for (int r = 0; r < 2; r++) {
            int rw = rowq + r * 64;
            float4 va = make_float4(0, 0, 0, 0), vb = make_float4(0, 0, 0, 0);
            if (k4 < rowLen) {
                va = *(const float4*)&Ab[(size_t)rw * ldf + k4];
                vb = *(const float4*)&Bb[(size_t)rw * ldf + k4];
            }
            As[0][k4 + 0][rw] = va.x; As[0][k4 + 1][rw] = va.y;
            As[0][k4 + 2][rw] = va.z; As[0][k4 + 3][rw] = va.w;
            Bs[0][k4 + 0][rw] = vb.x; Bs[0][k4 + 1][rw] = vb.y;
            Bs[0][k4 + 2][rw] = vb.z; Bs[0][k4 + 3][rw] = vb.w;
        }
    }
    __syncthreads();
    int buf = 0;
    for (int it = 0; it < KIT; ++it) {
        float4 ra[2], rb[2];
        bool more = (it + 1 < KIT);
        if (more) {
            int k0 = (it + 1) << 4;
#pragma unroll
            for (int r = 0; r < 2; r++) {
                int rw = rowq + r * 64;
                ra[r] = make_float4(0, 0, 0, 0);
                rb[r] = make_float4(0, 0, 0, 0);
                if (k0 + k4 < rowLen) {
                    ra[r] = *(const float4*)&Ab[(size_t)rw * ldf + k0 + k4];
                    rb[r] = *(const float4*)&Bb[(size_t)rw * ldf + k0 + k4];
                }
            }
        }
#pragma unroll
        for (int k = 0; k < 16; k++) {
            float4 a0 = *(const float4*)&As[buf][k][ty * 4];
            float4 a1 = *(const float4*)&As[buf][k][64 + ty * 4];
            float4 b0 = *(const float4*)&Bs[buf][k][tx * 4];
            float4 b1 = *(const float4*)&Bs[buf][k][64 + tx * 4];
            float av[8] = {a0.x, a0.y, a0.z, a0.w, a1.x, a1.y, a1.z, a1.w};
            float bv[8] = {b0.x, b0.y, b0.z, b0.w, b1.x, b1.y, b1.z, b1.w};
#pragma unroll
            for (int i = 0; i < 8; i++)
#pragma unroll
                for (int j = 0; j < 8; j++) acc[i][j] += av[i] * bv[j];
        }
        if (more) {
            int nb2 = buf ^ 1;
#pragma unroll
            for (int r = 0; r < 2; r++) {
                int rw = rowq + r * 64;
                As[nb2][k4 + 0][rw] = ra[r].x; As[nb2][k4 + 1][rw] = ra[r].y;
                As[nb2][k4 + 2][rw] = ra[r].z; As[nb2][k4 + 3][rw] = ra[r].w;
                Bs[nb2][k4 + 0][rw] = rb[r].x; Bs[nb2][k4 + 1][rw] = rb[r].y;
                Bs[nb2][k4 + 2][rw] = rb[r].z; Bs[nb2][k4 + 3][rw] = rb[r].w;
            }
            __syncthreads();
            buf = nb2;
        }
    }
    int mA = m0 + tx * 4, mB = m0 + 64 + tx * 4;
    float xmA[4], xmB[4];
#pragma unroll
    for (int j = 0; j < 4; j++) {
        xmA[j] = g_xx[b * N_PTS + mA + j];
        xmB[j] = g_xx[b * N_PTS + mB + j];
    }
#pragma unroll
    for (int i = 0; i < 8; i++) {
        int n = n0 + (i < 4 ? ty * 4 + i : 64 + ty * 4 + (i - 4));
        float xn = g_xx[b * N_PTS + n];
        uint4 o0, o1;
        o0.x = fkey(2.f * acc[i][0] - xn - xmA[0]);
        o0.y = fkey(2.f * acc[i][1] - xn - xmA[1]);
        o0.z = fkey(2.f * acc[i][2] - xn - xmA[2]);
        o0.w = fkey(2.f * acc[i][3] - xn - xmA[3]);
        o1.x = fkey(2.f * acc[i][4] - xn - xmB[0]);
        o1.y = fkey(2.f * acc[i][5] - xn - xmB[1]);
        o1.z = fkey(2.f * acc[i][6] - xn - xmB[2]);
        o1.w = fkey(2.f * acc[i][7] - xn - xmB[3]);
        size_t base = (size_t)b * N_PTS * N_PTS + (size_t)n * N_PTS;
        *(uint4*)&g_pd[base + mA] = o0;
        *(uint4*)&g_pd[base + mB] = o1;
    }
}

// ---------------- generic GEMM (FFMA) for the PQ gemms ----------------
__global__ __launch_bounds__(256, 2) void sgemm_wn(const float* __restrict__ A, int lda,
                                                   int K, const float* __restrict__ B,
                                                   int ldb, int rowLenB,
                                                   float* __restrict__ C, int ldc) {
    __shared__ float As[2][16][132];
    __shared__ float Bs[2][16][132];
    int tid = threadIdx.x, tx = tid & 15, ty = tid >> 4;
    int n0 = blockIdx.x * 128, m0 = blockIdx.y * 128;
    const float* Ab = A + (size_t)m0 * lda;
    const float* Bb = B + (size_t)n0 * ldb;
    int k4 = (tid & 3) * 4, rowq = tid >> 2;
    int KIT = (K + 15) >> 4;
    float acc[8][8] = {};
    {
#pragma unroll
        for (int r = 0; r < 8; r++) {
            int m = tx + r * 16;
            As[0][ty][m] = (ty < K) ? Ab[(size_t)m * lda + ty] : 0.f;
        }
#pragma unroll
        for (int r = 0; r < 2; r++) {
            int rw = rowq + r * 64;
            float4 v = make_float4(0, 0, 0, 0);
            if (k4 < rowLenB) v = *(const float4*)&Bb[(size_t)rw * ldb + k4];
            Bs[0][k4 + 0][rw] = v.x; Bs[0][k4 + 1][rw] = v.y;
            Bs[0][k4 + 2][rw] = v.z; Bs[0][k4 + 3][rw] = v.w;
        }
    }
    __syncthreads();
    int buf = 0;
    for (int it = 0; it < KIT; ++it) {
        float ra[8];
        float4 rb[2];
        bool more = (it + 1 < KIT);
        if (more) {
            int k0 = (it + 1) << 4;
#pragma unroll
            for (int r = 0; r < 8; r++) {
                int m = tx + r * 16;
                ra[r] = (k0 + ty < K) ? Ab[(size_t)m * lda + k0 + ty] : 0.f;
            }
#pragma unroll
            for (int r = 0; r < 2; r++) {
                int rw = rowq + r * 64;
                rb[r] = make_float4(0, 0, 0, 0);
                if (k0 + k4 < rowLenB) rb[r] = *(const float4*)&Bb[(size_t)rw * ldb + k0 + k4];
            }
        }
#pragma unroll
        for (int k = 0; k < 16; k++) {
            float4 a0 = *(const float4*)&As[buf][k][ty * 4];
            float4 a1 = *(const float4*)&As[buf][k][64 + ty * 4];
            float4 b0 = *(const float4*)&Bs[buf][k][tx * 4];
            float4 b1 = *(const float4*)&Bs[buf][k][64 + tx * 4];
            float av[8] = {a0.x, a0.y, a0.z, a0.w, a1.x, a1.y, a1.z, a1.w};
            float bv[8] = {b0.x, b0.y, b0.z, b0.w, b1.x, b1.y, b1.z, b1.w};
#pragma unroll
            for (int i = 0; i < 8; i++)
#pragma unroll
                for (int j = 0; j < 8; j++) acc[i][j] += av[i] * bv[j];
        }
        if (more) {
            int nb2 = buf ^ 1;
#pragma unroll
            for (int r = 0; r < 8; r++) As[nb2][ty][tx + r * 16] = ra[r];
#pragma unroll
            for (int r = 0; r < 2; r++) {
                int rw = rowq + r * 64;
                Bs[nb2][k4 + 0][rw] = rb[r].x; Bs[nb2][k4 + 1][rw] = rb[r].y;
                Bs[nb2][k4 + 2][rw] = rb[r].z; Bs[nb2][k4 + 3][rw] = rb[r].w;
            }
            __syncthreads();
            buf = nb2;
        }
    }
#pragma unroll
    for (int i = 0; i < 8; i++) {
        int m = m0 + (i < 4 ? ty * 4 + i : 64 + ty * 4 + (i - 4));
        float4 v0 = make_float4(acc[i][0], acc[i][1], acc[i][2], acc[i][3]);
        float4 v1 = make_float4(acc[i][4], acc[i][5], acc[i][6], acc[i][7]);
        *(float4*)&C[(size_t)m * ldc + n0 + tx * 4] = v0;
        *(float4*)&C[(size_t)m * ldc + n0 + 64 + tx * 4] = v1;
    }
}

// ---------------- bf16 split helpers for conv5 ----------------
__global__ void split_w5(const float* __restrict__ w) {
    int i = blockIdx.x * 256 + threadIdx.x;
    if (i >= 1024 * HCH) return;
    float v = w[i];
    __nv_bfloat16 h = __float2bfloat16(v);
    g_Wh[i] = h;
    g_Wl[i] = __float2bfloat16(v - __bfloat162float(h));
}
__global__ void split_h() {
    int i = blockIdx.x * 256 + threadIdx.x;
    if (i >= NB2 * HCH) return;
    float v = g_Ht[i];
    __nv_bfloat16 h = __float2bfloat16(v);
    g_Hh[i] = h;
    g_Hl[i] = __float2bfloat16(v - __bfloat162float(h));
}

// ---------------- conv5 via mma.sync bf16 ----------------
__global__ __launch_bounds__(256) void conv5_mma(float* __restrict__ C) {
    __shared__ __nv_bfloat16 As[128][40];
    __shared__ __nv_bfloat16 Bs[128][40];
    int tid = threadIdx.x;
    int warp = tid >> 5, lane = tid & 31;
    int n0 = blockIdx.x * 128, m0 = blockIdx.y * 128;
    int wm = warp >> 2, wn = warp & 3;
    float acc[4][4][4];
#pragma unroll
    for (int i = 0; i < 4; i++)
#pragma unroll
        for (int j = 0; j < 4; j++)
#pragma unroll
            for (int k = 0; k < 4; k++) acc[i][j][k] = 0.f;
    uint32_t aBase = smem_to_u32(&As[0][0]);
    uint32_t bBase = smem_to_u32(&Bs[0][0]);

    for (int it = 0; it < 48; it++) {
        int t = it >> 4, k0 = (it & 15) << 5;
        const __nv_bfloat16* Ag = (t == 2) ? g_Wl : g_Wh;
        const __nv_bfloat16* Bg = (t == 1) ? g_Hl : g_Hh;
#pragma unroll
        for (int i = 0; i < 2; i++) {
            int blk = i * 256 + tid;
            int row = blk >> 2, cb = blk & 3;
            *(uint4*)((char*)&As[row][0] + cb * 16) =
                *(const uint4*)&Ag[(size_t)(m0 + row) * HCH + k0 + cb * 8];
            *(uint4*)((char*)&Bs[row][0] + cb * 16) =
                *(const uint4*)&Bg[(size_t)(n0 + row) * HCH + k0 + cb * 8];
        }
        __syncthreads();
#pragma unroll
        for (int kk = 0; kk < 2; kk++) {
            uint32_t a[4][4];
#pragma unroll
            for (int mf = 0; mf < 4; mf++) {
                int row = wm * 64 + mf * 16 + (lane & 7) + ((lane >> 3) & 1) * 8;
                int col = kk * 16 + (lane >> 4) * 8;
                uint32_t addr = aBase + (uint32_t)(row * 80 + col * 2);
                asm volatile(
                    "ldmatrix.sync.aligned.m8n8.x4.shared.b16 {%0,%1,%2,%3}, [%4];"
                    : "=r"(a[mf][0]), "=r"(a[mf][1]), "=r"(a[mf][2]), "=r"(a[mf][3])
                    : "r"(addr));
            }
            uint32_t b[4][2];
#pragma unroll
            for (int np = 0; np < 2; np++) {
                int row = wn * 32 + np * 16 + (lane & 7) + ((lane >> 4) & 1) * 8;
                int col = kk * 16 + ((lane >> 3) & 1) * 8;
                uint32_t addr = bBase + (uint32_t)(row * 80 + col * 2);
                asm volatile(
                    "ldmatrix.sync.aligned.m8n8.x4.shared.b16 {%0,%1,%2,%3}, [%4];"
                    : "=r"(b[np * 2][0]), "=r"(b[np * 2][1]), "=r"(b[np * 2 + 1][0]),
                      "=r"(b[np * 2 + 1][1])
                    : "r"(addr));
            }
#pragma unroll
            for (int mf = 0; mf < 4; mf++)
#pragma unroll
                for (int nf = 0; nf < 4; nf++)
                    asm volatile(
                        "mma.sync.aligned.m16n8k16.row.col.f32.bf16.bf16.f32 "
                        "{%0,%1,%2,%3}, {%4,%5,%6,%7}, {%8,%9}, {%0,%1,%2,%3};"
                        : "+f"(acc[mf][nf][0]), "+f"(acc[mf][nf][1]),
                          "+f"(acc[mf][nf][2]), "+f"(acc[mf][nf][3])
                        : "r"(a[mf][0]), "r"(a[mf][1]), "r"(a[mf][2]), "r"(a[mf][3]),
                          "r"(b[nf][0]), "r"(b[nf][1]));
        }
        __syncthreads();
    }
    int g = lane >> 2, tq = lane & 3;
#pragma unroll
    for (int mf = 0; mf < 4; mf++)
#pragma unroll
        for (int nf = 0; nf < 4; nf++) {
            int o0 = m0 + wm * 64 + mf * 16 + g;
            int p = n0 + wn * 32 + nf * 8 + tq * 2;
            *(float2*)&C[(size_t)o0 * NB2 + p] =
                make_float2(acc[mf][nf][0], acc[mf][nf][1]);
            *(float2*)&C[(size_t)(o0 + 8) * NB2 + p] =
                make_float2(acc[mf][nf][2], acc[mf][nf][3]);
        }
}

// ---------------- top-20 per row via bucket select ----------------
__global__ __launch_bounds__(256) void topk_kernel() {
    int r = blockIdx.x;
    const unsigned* row = g_pd + (size_t)r * N_PTS;
    __shared__ unsigned long long cand[N_PTS];
    __shared__ int hist[132];
    __shared__ int sB, cnts[2];
    int tid = threadIdx.x;
    if (tid < 132) hist[tid] = 0;
    if (tid < 2) cnts[tid] = 0;
    __syncthreads();
    unsigned vals[8];
#pragma unroll
    for (int i = 0; i < 8; i++) {
        unsigned u = row[tid + i * 256];
        vals[i] = u;
        atomicAdd(&hist[u >> 24], 1);
    }
    __syncthreads();
    if (tid == 0) {
        int c = 0, bk = 128;
        while (bk > 0 && c + hist[bk] < KNN) { c += hist[bk]; bk--; }
        sB = bk;
    }
    __syncthreads();
    unsigned Bl = (unsigned)sB;
#pragma unroll
    for (int i = 0; i < 8; i++) {
        int m = tid + i * 256;
        unsigned u = vals[i];
        unsigned bk = u >> 24;
        if (bk > Bl) {
            int slot = atomicAdd(&cnts[0], 1);
            g_idx[r * KNN + slot] = m;
        } else if (bk == Bl) {
            int slot = atomicAdd(&cnts[1], 1);
            cand[slot] = ((unsigned long long)u << 32) | (unsigned)(0xFFFFFFFFu - m);
        }
    }
    __syncthreads();
    if (tid < 32) {
        int base = cnts[0];
        int cnt = cnts[1];
        int need = KNN - base;
        for (int it = 0; it < need; it++) {
            unsigned long long best = 0;
            for (int j = tid; j < cnt; j += 32) {
                unsigned long long k = cand[j];
                if (k > best) best = k;
            }
#pragma unroll
            for (int s = 16; s; s >>= 1) {
                unsigned long long o = __shfl_xor_sync(0xffffffffu, best, s);
                if (o > best) best = o;
            }
            if (tid == 0)
                g_idx[r * KNN + base + it] =
                    (int)(0xFFFFFFFFu - (unsigned)(best & 0xFFFFFFFFull));
            for (int j = tid; j < cnt; j += 32)
                if (cand[j] == best) cand[j] = 0;
            __syncwarp();
        }
    }
}

// ---------------- pack [W1 ; W2-W1] ----------------
__global__ void build_wpq(const float* __restrict__ W, int Cout, int Cin) {
    int i = blockIdx.x * 256 + threadIdx.x;
    if (i >= Cout * Cin) return;
    int o = i / Cin, c = i - o * Cin;
    float w1 = W[(size_t)o * 2 * Cin + c];
    float w2 = W[(size_t)o * 2 * Cin + Cin + c];
    g_Wpq[(size_t)o * Cin + c] = w1;
    g_Wpq[(size_t)(Cout + o) * Cin + c] = w2 - w1;
}

// ---------------- neighbor reduce: partial stats + M = max_k P[nb] + Q ----------------
__global__ void nbr_reduce(int Cout) {
    int o = blockIdx.x, b = blockIdx.y;  // b in 0..7
    __shared__ float sp[N_PTS];
    __shared__ double rs1[256], rs2[256];
    int tid = threadIdx.x;
    const float* Prow = g_PQ + (size_t)o * NB2 + b * N_PTS;
    const float* Qrow = g_PQ + (size_t)(Cout + o) * NB2 + b * N_PTS;
    for (int i = tid; i < N_PTS; i += 256) sp[i] = Prow[i];
    __syncthreads();
    double s1 = 0.0, s2 = 0.0;
    for (int n = tid; n < N_PTS; n += 256) {
        const int* ip = g_idx + (size_t)(b * N_PTS + n) * KNN;
        float mx = -1e30f, su = 0.f, su2 = 0.f;
#pragma unroll
        for (int k = 0; k < KNN; k++) {
            float p = sp[ip[k]];
            mx = fmaxf(mx, p);
            su += p;
            su2 += p * p;
        }
        float q = Qrow[n];
        g_M[(size_t)o * NB2 + b * N_PTS + n] = mx + q;
        s1 += (double)su + 20.0 * (double)q;
        s2 += (double)su2 + 2.0 * (double)q * (double)su + 20.0 * (double)q * (double)q;
    }
    rs1[tid] = s1;
    rs2[tid] = s2;
    __syncthreads();
    for (int st = 128; st; st >>= 1) {
        if (tid < st) { rs1[tid] += rs1[tid + st]; rs2[tid] += rs2[tid + st]; }
        __syncthreads();
    }
    if (!tid) {
        g_ps[o * 8 + b] = rs1[0];
        g_pq2[o * 8 + b] = rs2[0];
    }
}

// edge-layer BN: per slot s (0/1) sum parts s*4..s*4+3
__global__ void finalize_bn_edge(const float* __restrict__ gam,
                                 const float* __restrict__ bet, int Cout) {
    int o = blockIdx.x * 256 + threadIdx.x;
    if (o >= Cout) return;
#pragma unroll
    for (int s = 0; s < 2; s++) {
        double su = 0.0, q = 0.0;
        for (int j = 0; j < 4; j++) {
            su += g_ps[o * 8 + s * 4 + j];
            q += g_pq2[o * 8 + s * 4 + j];
        }
        double m = su / (double)PPOS;
        double v = q / (double)PPOS - m * m;
        float sc = (float)((double)gam[o] / sqrt(v + 1e-5));
        g_scale[s * 1024 + o] = sc;
        g_shift[s * 1024 + o] = bet[o] - (float)m * sc;
    }
}

// ---------------- apply BN+LReLU, transpose M (o-major) -> Ht (pos-major) ----------------
// 32x32 tiles, both sides coalesced
__global__ __launch_bounds__(256) void apply_bn_t(int Cout, int dstoff) {
    __shared__ float tile[32][33];
    int bn0 = blockIdx.x * 32, o0 = blockIdx.y * 32;
    int tx = threadIdx.x & 31, ty = threadIdx.x >> 5;  // 32 x 8
    int slot = bn0 >> 13;
    const float* sc = g_scale + slot * 1024;
    const float* sh = g_shift + slot * 1024;
#pragma unroll
    for (int r = 0; r < 4; r++) {
        int ol = ty + r * 8;
        int o = o0 + ol;
        float v = g_M[(size_t)o * NB2 + bn0 + tx] * sc[o] + sh[o];
        tile[ol][tx] = v > 0.f ? v : NEG_SLOPE * v;
    }
    __syncthreads();
#pragma unroll
    for (int r = 0; r < 4; r++) {
        int bl = ty + r * 8;
        g_Ht[(size_t)(bn0 + bl) * HCH + dstoff + o0 + tx] = tile[tx][bl];
    }
}

// ---------------- conv5 partial stats (16 parts; parts 0-7 slot0, 8-15 slot1) ----------------
__global__ void stats_y5() {
    int o = blockIdx.x;
    size_t base = (size_t)o * NB2 + blockIdx.y * 1024;
    double s = 0.0, q = 0.0;
    for (int i = threadIdx.x; i < 1024; i += 256) {
        double v = (double)g_Y5[base + i];
        s += v;
        q += v * v;
    }
    __shared__ double sh[256];
    int tid = threadIdx.x;
    sh[tid] = s;
    __syncthreads();
    for (int st = 128; st; st >>= 1) {
        if (tid < st) sh[tid] += sh[tid + st];
        __syncthreads();
    }
    double ts = sh[0];
    __syncthreads();
    sh[tid] = q;
    __syncthreads();
    for (int st = 128; st; st >>= 1) {
        if (tid < st) sh[tid] += sh[tid + st];
        __syncthreads();
    }
    if (!tid) {
        g_ps[o * 16 + blockIdx.y] = ts;
        g_pq2[o * 16 + blockIdx.y] = sh[0];
    }
}

__global__ void finalize_bn5(const float* __restrict__ gam,
                             const float* __restrict__ bet) {
    int o = blockIdx.x * 256 + threadIdx.x;
    if (o >= 1024) return;
#pragma unroll
    for (int s = 0; s < 2; s++) {
        double su = 0.0, q = 0.0;
        for (int j = 0; j < 8; j++) {
            su += g_ps[o * 16 + s * 8 + j];
            q += g_pq2[o * 16 + s * 8 + j];
        }
        double m = su / 8192.0;
        double v = q / 8192.0 - m * m;
        float sc = (float)((double)gam[o] / sqrt(v + 1e-5));
        g_scale[s * 1024 + o] = sc;
        g_shift[s * 1024 + o] = bet[o] - (float)m * sc;
    }
}

// ---------------- conv5 BN + LReLU + max & mean over N -> z ----------------
__global__ void zmaxmean_kernel() {
    int o = blockIdx.x, b = blockIdx.y;  // b in 0..7
    int slot = b >> 2;
    const float* row = g_Y5 + (size_t)o * NB2 + (size_t)b * N_PTS;
    float sc = g_scale[slot * 1024 + o], sh = g_shift[slot * 1024 + o];
    float mx = -1e30f, sm = 0.f;
    for (int n = threadIdx.x; n < N_PTS; n += 256) {
        float v = row[n] * sc + sh;
        v = v > 0.f ? v : NEG_SLOPE * v;
        mx = fmaxf(mx, v);
        sm += v;
    }
    __shared__ float smx[256];
    __shared__ float ssm[256];
    int tid = threadIdx.x;
    smx[tid] = mx;
    ssm[tid] = sm;
    __syncthreads();
    for (int st = 128; st; st >>= 1) {
        if (tid < st) {
            smx[tid] = fmaxf(smx[tid], smx[tid + st]);
            ssm[tid] += ssm[tid + st];
        }
        __syncthreads();
    }
    if (!tid) {
        g_z[b * 2048 + o] = smx[0];
        g_z[b * 2048 + 1024 + o] = ssm[0] * (1.f / 2048.f);
    }
}

// ---------------- MLP head ----------------
__global__ void head_kernel(const float* __restrict__ lw1, const float* __restrict__ lb1,
                            const float* __restrict__ lw2, const float* __restrict__ lb2,
                            const float* __restrict__ lw3, const float* __restrict__ lb3,
                            int slot, float* __restrict__ out) {
    int b = blockIdx.x, tid = threadIdx.x;
    __shared__ float zs[2048];
    __shared__ float z1[256];
    __shared__ float z2[64];
    for (int i = tid; i < 2048; i += 256) zs[i] = g_z[(slot * 4 + b) * 2048 + i];
    __syncthreads();
    {
        float a = lb1[tid];
        const float* wr = lw1 + (size_t)tid * 2048;
        for (int c = 0; c < 2048; c++) a += wr[c] * zs[c];
        z1[tid] = a;
    }
    __syncthreads();
    if (tid < 64) {
        float a = lb2[tid];
        const float* wr = lw2 + (size_t)tid * 256;
        for (int c = 0; c < 256; c++) a += wr[c] * z1[c];
        z2[tid] = a;
    }
    __syncthreads();
    if (tid < 10) {
        float a = lb3[tid];
        const float* wr = lw3 + (size_t)tid * 64;
        for (int c = 0; c < 64; c++) a += wr[c] * z2[c];
        g_e[slot * 40 + b * 10 + tid] = a;
        out[6404 + slot * 40 + b * 10 + tid] = a;
    }
}

// ---------------- cluster assignment ----------------
__global__ void cluster_kernel(const float* __restrict__ cw, int slot,
                               float* __restrict__ out) {
    int b = blockIdx.x, j = threadIdx.x;
    __shared__ float es[10];
    __shared__ float red[1024];
    if (j < 10) es[j] = g_e[slot * 40 + b * 10 + j];
    __syncthreads();
    float xd = 0.f, qn = 0.f;
    if (j < 800) {
#pragma unroll
        for (int t = 0; t < 10; t++) {
            float d = es[t] - cw[j * 10 + t];
            xd += d * d;
        }
        qn = 1.f / (1.f + xd);
    }
    red[j] = qn;
    __syncthreads();
    for (int st = 512; st; st >>= 1) {
        if (j < st) red[j] += red[j + st];
        __syncthreads();
    }
    float tot = red[0];
    if (j < 800) {
        out[4 + slot * 3200 + b * 800 + j] = qn / tot;
        if (!slot) out[6484 + b * 800 + j] = xd;
    }
}

__global__ void sim_kernel(float* __restrict__ out) {
    int b = threadIdx.x;
    if (b < 4) {
        float s = 0.f;
        for (int j = 0; j < 10; j++) {
            float d = g_e[b * 10 + j] - g_e[40 + b * 10 + j] + 1e-6f;
            s += d * d;
        }
        out[b] = sqrtf(s);
    }
}

// ---------------- host orchestration (single batched pass) ----------------
extern "C" void kernel_launch(void* const* d_in, const int* in_sizes, int n_in,
                              void* d_out, int out_size) {
    const float* x1 = (const float*)d_in[0];
    const float* x2 = (const float*)d_in[1];
    const float* Wl[4] = {(const float*)d_in[2], (const float*)d_in[5],
                          (const float*)d_in[8], (const float*)d_in[11]};
    const float* Gl[4] = {(const float*)d_in[3], (const float*)d_in[6],
                          (const float*)d_in[9], (const float*)d_in[12]};
    const float* Bl[4] = {(const float*)d_in[4], (const float*)d_in[7],
                          (const float*)d_in[10], (const float*)d_in[13]};
    const float* w5 = (const float*)d_in[14];
    const float* g5 = (const float*)d_in[15];
    const float* b5 = (const float*)d_in[16];
    const float* lw1 = (const float*)d_in[17];
    const float* lb1 = (const float*)d_in[18];
    const float* lw2 = (const float*)d_in[19];
    const float* lb2 = (const float*)d_in[20];
    const float* lw3 = (const float*)d_in[21];
    const float* lb3 = (const float*)d_in[22];
    const float* cw = (const float*)d_in[23];
    float* out = (float*)d_out;

    const int Cin[4] = {3, 64, 64, 128};
    const int Cout[4] = {64, 64, 128, 256};
    const int choff[4] = {0, 0, 64, 128};
    const int dstoff[4] = {0, 64, 128, 256};

    float* xtp = nullptr;
    float* htp = nullptr;
    float* wpq = nullptr;
    float* pq = nullptr;
    float* y5 = nullptr;
    cudaGetSymbolAddress((void**)&xtp, g_Xt);
    cudaGetSymbolAddress((void**)&htp, g_Ht);
    cudaGetSymbolAddress((void**)&wpq, g_Wpq);
    cudaGetSymbolAddress((void**)&pq, g_PQ);
    cudaGetSymbolAddress((void**)&y5, g_Y5);

    split_w5<<<(1024 * HCH + 255) / 256, 256>>>(w5);
    transpose_x<<<NB2 / 256, 256>>>(x1, x2);

    for (int l = 0; l < 4; l++) {
        const float* F = (l == 0) ? xtp : (htp + choff[l]);
        int ldf = (l == 0) ? 4 : HCH;
        int rowLen = (l == 0) ? 4 : Cin[l];
        size_t bstride = (size_t)N_PTS * ldf;
        compute_xx<<<NB2 / 256, 256>>>(F, ldf, Cin[l]);
        pd_gemm2<<<dim3(16, 16, B2), 256>>>(F, ldf, rowLen, Cin[l], bstride);
        topk_kernel<<<NB2, 256>>>();
        build_wpq<<<(Cout[l] * Cin[l] + 255) / 256, 256>>>(Wl[l], Cout[l], Cin[l]);
        sgemm_wn<<<dim3(NB2 / 128, 2 * Cout[l] / 128), 256>>>(wpq, Cin[l], Cin[l], F,
                                                              ldf, rowLen, pq, NB2);
        nbr_reduce<<<dim3(Cout[l], B2), 256>>>(Cout[l]);
        finalize_bn_edge<<<1, 256>>>(Gl[l], Bl[l], Cout[l]);
        apply_bn_t<<<dim3(NB2 / 32, Cout[l] / 32), 256>>>(Cout[l], dstoff[l]);
    }
    split_h<<<(NB2 * HCH + 255) / 256, 256>>>();
    conv5_mma<<<dim3(NB2 / 128, 1024 / 128), 256>>>(y5);
    stats_y5<<<dim3(1024, 16), 256>>>();
    finalize_bn5<<<4, 256>>>(g5, b5);
    zmaxmean_kernel<<<dim3(1024, B2), 256>>>();
    for (int s = 0; s < 2; s++) {
        head_kernel<<<4, 256>>>(lw1, lb1, lw2, lb2, lw3, lb3, s, out);
        cluster_kernel<<<4, 1024>>>(cw, s, out);
    }
    sim_kernel<<<1, 32>>>(out);
}

// round 16
// speedup vs baseline: 1.5194x; 1.2074x over previous
#include <cuda_runtime.h>
#include <cuda_bf16.h>
#include <cstdint>
#include <math.h>

#define N_PTS 2048
#define B2 8                        // both inputs batched: 2 slots x 4
#define NB2 (B2 * N_PTS)            // 16384 positions
#define KNN 20
#define PPOS (4 * N_PTS * KNN)      // per-slot BN count: 163840
#define HCH 512
#define NEG_SLOPE 0.2f

// ---------------- scratch (static device globals) ----------------
__device__ unsigned g_pd[B2 * N_PTS * N_PTS];   // 128 MB, ordered u32 keys
__device__ float  g_xx[NB2];
__device__ int    g_idx[NB2 * KNN];
__device__ float  g_Xt[NB2 * 4];
__device__ float  g_Ht[NB2 * HCH];
__device__ float  g_Wpq[512 * 128];
__device__ float  g_PQ[512 * NB2 + 8];
__device__ float  g_M[256 * NB2];
__device__ float  g_Y5[1024 * NB2];
__device__ double g_ps[1024 * 16], g_pq2[1024 * 16];
__device__ float  g_scale[2048], g_shift[2048];
__device__ float  g_z[B2 * 2048];
__device__ float  g_e[2 * 4 * 10];
__device__ __nv_bfloat16 g_Wh[1024 * HCH], g_Wl[1024 * HCH];
__device__ __nv_bfloat16 g_Hh[NB2 * HCH], g_Hl[NB2 * HCH];

__device__ __forceinline__ unsigned fkey(float v) {
    unsigned u = __float_as_uint(v);
    return ((int)u < 0) ? ~u : (u | 0x80000000u);
}
__device__ __forceinline__ uint32_t smem_to_u32(const void* p) {
    uint32_t a;
    asm("{ .reg .u64 t; cvta.to.shared.u64 t, %1; cvt.u32.u64 %0, t; }" : "=r"(a)
        : "l"(p));
    return a;
}
#define CPA16(s, g) \
    asm volatile("cp.async.ca.shared.global [%0], [%1], 16;" :: "r"(s), "l"(g))
#define CPC() asm volatile("cp.async.commit_group;" ::: "memory")
#define CPW(N) asm volatile("cp.async.wait_group %0;" :: "n"(N) : "memory")

// ---------------- build pos-major x (both inputs) with zero pad ----------------
__global__ void transpose_x(const float* __restrict__ x1, const float* __restrict__ x2) {
    int i = blockIdx.x * 256 + threadIdx.x;
    if (i >= NB2) return;
    int b = i >> 11, n = i & 2047;
    const float* x = (b < 4) ? x1 : x2;
    int bb = b & 3;
    float4 v;
    v.x = x[(bb * 3 + 0) * N_PTS + n];
    v.y = x[(bb * 3 + 1) * N_PTS + n];
    v.z = x[(bb * 3 + 2) * N_PTS + n];
    v.w = 0.f;
    *(float4*)&g_Xt[i * 4] = v;
}

// ---------------- xx[bn] = sum_c F[bn][c]^2 ----------------
__global__ void compute_xx(const float* __restrict__ F, int ldf, int K) {
    int i = blockIdx.x * 256 + threadIdx.x;
    if (i >= NB2) return;
    const float* row = F + (size_t)i * ldf;
    float s = 0.f;
    for (int c = 0; c < K; c++) { float v = row[c]; s += v * v; }
    g_xx[i] = s;
}

// ---------------- pd GEMM: writes ordered u32 keys ----------------
__global__ __launch_bounds__(256, 2) void pd_gemm2(const float* __restrict__ F, int ldf,
                                                   int rowLen, int K, size_t bstride) {
    __shared__ float As[2][16][132];
    __shared__ float Bs[2][16][132];
    int tid = threadIdx.x, tx = tid & 15, ty = tid >> 4;
    int n0 = blockIdx.y * 128, m0 = blockIdx.x * 128;
    int b = blockIdx.z;
    const float* Ab = F + (size_t)b * bstride + (size_t)n0 * ldf;
    const float* Bb = F + (size_t)b * bstride + (size_t)m0 * ldf;
    int k4 = (tid & 3) * 4, rowq = tid >> 2;
    int KIT = (K + 15) >> 4;
    float acc[8][8] = {};
    {
#pragma unroll
        for (int r = 0; r < 2; r++) {
            int rw = rowq + r * 64;
            float4 va = make_float4(0, 0, 0, 0), vb = make_float4(0, 0, 0, 0);
            if (k4 < rowLen) {
                va = *(const float4*)&Ab[(size_t)rw * ldf + k4];
                vb = *(const float4*)&Bb[(size_t)rw * ldf + k4];
            }
            As[0][k4 + 0][rw] = va.x; As[0][k4 + 1][rw] = va.y;
            As[0][k4 + 2][rw] = va.z; As[0][k4 + 3][rw] = va.w;
            Bs[0][k4 + 0][rw] = vb.x; Bs[0][k4 + 1][rw] = vb.y;
            Bs[0][k4 + 2][rw] = vb.z; Bs[0][k4 + 3][rw] = vb.w;
        }
    }
    __syncthreads();
    int buf = 0;
    for (int it = 0; it < KIT; ++it) {
        float4 ra[2], rb[2];
        bool more = (it + 1 < KIT);
        if (more) {
            int k0 = (it + 1) << 4;
#pragma unroll
            for (int r = 0; r < 2; r++) {
                int rw = rowq + r * 64;
                ra[r] = make_float4(0, 0, 0, 0);
                rb[r] = make_float4(0, 0, 0, 0);
                if (k0 + k4 < rowLen) {
                    ra[r] = *(const float4*)&Ab[(size_t)rw * ldf + k0 + k4];
                    rb[r] = *(const float4*)&Bb[(size_t)rw * ldf + k0 + k4];
                }
            }
        }
#pragma unroll
        for (int k = 0; k < 16; k++) {
            float4 a0 = *(const float4*)&As[buf][k][ty * 4];
            float4 a1 = *(const float4*)&As[buf][k][64 + ty * 4];
            float4 b0 = *(const float4*)&Bs[buf][k][tx * 4];
            float4 b1 = *(const float4*)&Bs[buf][k][64 + tx * 4];
            float av[8] = {a0.x, a0.y, a0.z, a0.w, a1.x, a1.y, a1.z, a1.w};
            float bv[8] = {b0.x, b0.y, b0.z, b0.w, b1.x, b1.y, b1.z, b1.w};
#pragma unroll
            for (int i = 0; i < 8; i++)
#pragma unroll
                for (int j = 0; j < 8; j++) acc[i][j] += av[i] * bv[j];
        }
        if (more) {
            int nb2 = buf ^ 1;
#pragma unroll
            for (int r = 0; r < 2; r++) {
                int rw = rowq + r * 64;
                As[nb2][k4 + 0][rw] = ra[r].x; As[nb2][k4 + 1][rw] = ra[r].y;
                As[nb2][k4 + 2][rw] = ra[r].z; As[nb2][k4 + 3][rw] = ra[r].w;
                Bs[nb2][k4 + 0][rw] = rb[r].x; Bs[nb2][k4 + 1][rw] = rb[r].y;
                Bs[nb2][k4 + 2][rw] = rb[r].z; Bs[nb2][k4 + 3][rw] = rb[r].w;
            }
            __syncthreads();
            buf = nb2;
        }
    }
    int mA = m0 + tx * 4, mB = m0 + 64 + tx * 4;
    float xmA[4], xmB[4];
#pragma unroll
    for (int j = 0; j < 4; j++) {
        xmA[j] = g_xx[b * N_PTS + mA + j];
        xmB[j] = g_xx[b * N_PTS + mB + j];
    }
#pragma unroll
    for (int i = 0; i < 8; i++) {
        int n = n0 + (i < 4 ? ty * 4 + i : 64 + ty * 4 + (i - 4));
        float xn = g_xx[b * N_PTS + n];
        uint4 o0, o1;
        o0.x = fkey(2.f * acc[i][0] - xn - xmA[0]);
        o0.y = fkey(2.f * acc[i][1] - xn - xmA[1]);
        o0.z = fkey(2.f * acc[i][2] - xn - xmA[2]);
        o0.w = fkey(2.f * acc[i][3] - xn - xmA[3]);
        o1.x = fkey(2.f * acc[i][4] - xn - xmB[0]);
        o1.y = fkey(2.f * acc[i][5] - xn - xmB[1]);
        o1.z = fkey(2.f * acc[i][6] - xn - xmB[2]);
        o1.w = fkey(2.f * acc[i][7] - xn - xmB[3]);
        size_t base = (size_t)b * N_PTS * N_PTS + (size_t)n * N_PTS;
        *(uint4*)&g_pd[base + mA] = o0;
        *(uint4*)&g_pd[base + mB] = o1;
    }
}

// ---------------- generic GEMM (FFMA) for the PQ gemms ----------------
__global__ __launch_bounds__(256, 2) void sgemm_wn(const float* __restrict__ A, int lda,
                                                   int K, const float* __restrict__ B,
                                                   int ldb, int rowLenB,
                                                   float* __restrict__ C, int ldc) {
    __shared__ float As[2][16][132];
    __shared__ float Bs[2][16][132];
    int tid = threadIdx.x, tx = tid & 15, ty = tid >> 4;
    int n0 = blockIdx.x * 128, m0 = blockIdx.y * 128;
    const float* Ab = A + (size_t)m0 * lda;
    const float* Bb = B + (size_t)n0 * ldb;
    int k4 = (tid & 3) * 4, rowq = tid >> 2;
    int KIT = (K + 15) >> 4;
    float acc[8][8] = {};
    {
#pragma unroll
        for (int r = 0; r < 8; r++) {
            int m = tx + r * 16;
            As[0][ty][m] = (ty < K) ? Ab[(size_t)m * lda + ty] : 0.f;
        }
#pragma unroll
        for (int r = 0; r < 2; r++) {
            int rw = rowq + r * 64;
            float4 v = make_float4(0, 0, 0, 0);
            if (k4 < rowLenB) v = *(const float4*)&Bb[(size_t)rw * ldb + k4];
            Bs[0][k4 + 0][rw] = v.x; Bs[0][k4 + 1][rw] = v.y;
            Bs[0][k4 + 2][rw] = v.z; Bs[0][k4 + 3][rw] = v.w;
        }
    }
    __syncthreads();
    int buf = 0;
    for (int it = 0; it < KIT; ++it) {
        float ra[8];
        float4 rb[2];
        bool more = (it + 1 < KIT);
        if (more) {
            int k0 = (it + 1) << 4;
#pragma unroll
            for (int r = 0; r < 8; r++) {
                int m = tx + r * 16;
                ra[r] = (k0 + ty < K) ? Ab[(size_t)m * lda + k0 + ty] : 0.f;
            }
#pragma unroll
            for (int r = 0; r < 2; r++) {
                int rw = rowq + r * 64;
                rb[r] = make_float4(0, 0, 0, 0);
                if (k0 + k4 < rowLenB) rb[r] = *(const float4*)&Bb[(size_t)rw * ldb + k0 + k4];
            }
        }
#pragma unroll
        for (int k = 0; k < 16; k++) {
            float4 a0 = *(const float4*)&As[buf][k][ty * 4];
            float4 a1 = *(const float4*)&As[buf][k][64 + ty * 4];
            float4 b0 = *(const float4*)&Bs[buf][k][tx * 4];
            float4 b1 = *(const float4*)&Bs[buf][k][64 + tx * 4];
            float av[8] = {a0.x, a0.y, a0.z, a0.w, a1.x, a1.y, a1.z, a1.w};
            float bv[8] = {b0.x, b0.y, b0.z, b0.w, b1.x, b1.y, b1.z, b1.w};
#pragma unroll
            for (int i = 0; i < 8; i++)
#pragma unroll
                for (int j = 0; j < 8; j++) acc[i][j] += av[i] * bv[j];
        }
        if (more) {
            int nb2 = buf ^ 1;
#pragma unroll
            for (int r = 0; r < 8; r++) As[nb2][ty][tx + r * 16] = ra[r];
#pragma unroll
            for (int r = 0; r < 2; r++) {
                int rw = rowq + r * 64;
                Bs[nb2][k4 + 0][rw] = rb[r].x; Bs[nb2][k4 + 1][rw] = rb[r].y;
                Bs[nb2][k4 + 2][rw] = rb[r].z; Bs[nb2][k4 + 3][rw] = rb[r].w;
            }
            __syncthreads();
            buf = nb2;
        }
    }
#pragma unroll
    for (int i = 0; i < 8; i++) {
        int m = m0 + (i < 4 ? ty * 4 + i : 64 + ty * 4 + (i - 4));
        float4 v0 = make_float4(acc[i][0], acc[i][1], acc[i][2], acc[i][3]);
        float4 v1 = make_float4(acc[i][4], acc[i][5], acc[i][6], acc[i][7]);
        *(float4*)&C[(size_t)m * ldc + n0 + tx * 4] = v0;
        *(float4*)&C[(size_t)m * ldc + n0 + 64 + tx * 4] = v1;
    }
}

// ---------------- bf16 split helpers ----------------
__global__ void split_w5(const float* __restrict__ w) {
    int i = blockIdx.x * 256 + threadIdx.x;
    if (i >= 1024 * HCH) return;
    float v = w[i];
    __nv_bfloat16 h = __float2bfloat16(v);
    g_Wh[i] = h;
    g_Wl[i] = __float2bfloat16(v - __bfloat162float(h));
}
__global__ void split_h() {
    int i = blockIdx.x * 256 + threadIdx.x;
    if (i >= NB2 * HCH) return;
    float v = g_Ht[i];
    __nv_bfloat16 h = __float2bfloat16(v);
    g_Hh[i] = h;
    g_Hl[i] = __float2bfloat16(v - __bfloat162float(h));
}

// ---------------- conv5 via mma.sync bf16, cp.async double-buffered ----------------
__global__ __launch_bounds__(256) void conv5_mma(float* __restrict__ C) {
    __shared__ __nv_bfloat16 As[2][128][40];
    __shared__ __nv_bfloat16 Bs[2][128][40];
    int tid = threadIdx.x;
    int warp = tid >> 5, lane = tid & 31;
    int n0 = blockIdx.x * 128, m0 = blockIdx.y * 128;
    int wm = warp >> 2, wn = warp & 3;
    float acc[4][4][4];
#pragma unroll
    for (int i = 0; i < 4; i++)
#pragma unroll
        for (int j = 0; j < 4; j++)
#pragma unroll
            for (int k = 0; k < 4; k++) acc[i][j][k] = 0.f;
    uint32_t aB[2] = {smem_to_u32(&As[0][0][0]), smem_to_u32(&As[1][0][0])};
    uint32_t bB[2] = {smem_to_u32(&Bs[0][0][0]), smem_to_u32(&Bs[1][0][0])};

    int blk0 = tid, blk1 = 256 + tid;
    int r0 = blk0 >> 2, c0 = (blk0 & 3) * 16;
    int r1 = blk1 >> 2, c1 = (blk1 & 3) * 16;

    // issue loads for chunk `it` into buffer bufi
    auto issue = [&](int it, int bufi) {
        int t = it >> 4, k0 = (it & 15) << 5;
        const __nv_bfloat16* Ag = (t == 2) ? g_Wl : g_Wh;
        const __nv_bfloat16* Bg = (t == 1) ? g_Hl : g_Hh;
        CPA16(aB[bufi] + r0 * 80 + c0, &Ag[(size_t)(m0 + r0) * HCH + k0 + (c0 >> 1)]);
        CPA16(aB[bufi] + r1 * 80 + c1, &Ag[(size_t)(m0 + r1) * HCH + k0 + (c1 >> 1)]);
        CPA16(bB[bufi] + r0 * 80 + c0, &Bg[(size_t)(n0 + r0) * HCH + k0 + (c0 >> 1)]);
        CPA16(bB[bufi] + r1 * 80 + c1, &Bg[(size_t)(n0 + r1) * HCH + k0 + (c1 >> 1)]);
        CPC();
    };
    issue(0, 0);
    for (int it = 0; it < 48; it++) {
        int bufi = it & 1;
        if (it + 1 < 48) {
            issue(it + 1, bufi ^ 1);
            CPW(1);
        } else {
            CPW(0);
        }
        __syncthreads();
#pragma unroll
        for (int kk = 0; kk < 2; kk++) {
            uint32_t a[4][4];
#pragma unroll
            for (int mf = 0; mf < 4; mf++) {
                int row = wm * 64 + mf * 16 + (lane & 7) + ((lane >> 3) & 1) * 8;
                int col = kk * 16 + (lane >> 4) * 8;
                uint32_t addr = aB[bufi] + (uint32_t)(row * 80 + col * 2);
                asm volatile(
                    "ldmatrix.sync.aligned.m8n8.x4.shared.b16 {%0,%1,%2,%3}, [%4];"
                    : "=r"(a[mf][0]), "=r"(a[mf][1]), "=r"(a[mf][2]), "=r"(a[mf][3])
                    : "r"(addr));
            }
            uint32_t b[4][2];
#pragma unroll
            for (int np = 0; np < 2; np++) {
                int row = wn * 32 + np * 16 + (lane & 7) + ((lane >> 4) & 1) * 8;
                int col = kk * 16 + ((lane >> 3) & 1) * 8;
                uint32_t addr = bB[bufi] + (uint32_t)(row * 80 + col * 2);
                asm volatile(
                    "ldmatrix.sync.aligned.m8n8.x4.shared.b16 {%0,%1,%2,%3}, [%4];"
                    : "=r"(b[np * 2][0]), "=r"(b[np * 2][1]), "=r"(b[np * 2 + 1][0]),
                      "=r"(b[np * 2 + 1][1])
                    : "r"(addr));
            }
#pragma unroll
            for (int mf = 0; mf < 4; mf++)
#pragma unroll
                for (int nf = 0; nf < 4; nf++)
                    asm volatile(
                        "mma.sync.aligned.m16n8k16.row.col.f32.bf16.bf16.f32 "
                        "{%0,%1,%2,%3}, {%4,%5,%6,%7}, {%8,%9}, {%0,%1,%2,%3};"
                        : "+f"(acc[mf][nf][0]), "+f"(acc[mf][nf][1]),
                          "+f"(acc[mf][nf][2]), "+f"(acc[mf][nf][3])
                        : "r"(a[mf][0]), "r"(a[mf][1]), "r"(a[mf][2]), "r"(a[mf][3]),
                          "r"(b[nf][0]), "r"(b[nf][1]));
        }
        __syncthreads();
    }
    int g = lane >> 2, tq = lane & 3;
#pragma unroll
    for (int mf = 0; mf < 4; mf++)
#pragma unroll
        for (int nf = 0; nf < 4; nf++) {
            int o0 = m0 + wm * 64 + mf * 16 + g;
            int p = n0 + wn * 32 + nf * 8 + tq * 2;
            *(float2*)&C[(size_t)o0 * NB2 + p] =
                make_float2(acc[mf][nf][0], acc[mf][nf][1]);
            *(float2*)&C[(size_t)(o0 + 8) * NB2 + p] =
                make_float2(acc[mf][nf][2], acc[mf][nf][3]);
        }
}

// ---------------- top-20 per row: two-level refine, parallel threshold scans ------
// Selected SET unordered (downstream reductions are permutation-invariant).
__global__ __launch_bounds__(256) void topk_kernel() {
    int r = blockIdx.x;
    const unsigned* row = g_pd + (size_t)r * N_PTS;
    __shared__ int hist[256], sufA[256], sufB[256];
    __shared__ unsigned long long cand[512];
    __shared__ unsigned long long red[256];
    __shared__ int cnts[2];
    int tid = threadIdx.x;
    hist[tid] = 0;
    if (tid < 2) cnts[tid] = 0;
    __syncthreads();
    unsigned vals[8];
#pragma unroll
    for (int i = 0; i < 8; i++) {
        unsigned u = row[tid + i * 256];
        vals[i] = u;
        atomicAdd(&hist[u >> 24], 1);
    }
    __syncthreads();
    // ---- level-1 parallel suffix scan ----
    int* src = sufA;
    int* dst = sufB;
    src[tid] = hist[tid];
    __syncthreads();
#pragma unroll
    for (int off = 1; off < 256; off <<= 1) {
        dst[tid] = src[tid] + ((tid + off < 256) ? src[tid + off] : 0);
        __syncthreads();
        int* t = src; src = dst; dst = t;
    }
    int b1 = __syncthreads_count(src[tid] >= KNN) - 1;   // suffix non-increasing
    int above1 = (b1 < 255) ? src[b1 + 1] : 0;
    int need2 = KNN - above1;
    // ---- level-2 histogram on bits [23:16] within bucket b1 ----
    hist[tid] = 0;
    __syncthreads();
#pragma unroll
    for (int i = 0; i < 8; i++) {
        unsigned u = vals[i];
        if ((int)(u >> 24) == b1) atomicAdd(&hist[(u >> 16) & 255], 1);
    }
    __syncthreads();
    src = sufA; dst = sufB;
    src[tid] = hist[tid];
    __syncthreads();
#pragma unroll
    for (int off = 1; off < 256; off <<= 1) {
        dst[tid] = src[tid] + ((tid + off < 256) ? src[tid + off] : 0);
        __syncthreads();
        int* t = src; src = dst; dst = t;
    }
    int b2 = __syncthreads_count(src[tid] >= need2) - 1;
    unsigned P = ((unsigned)b1 << 8) | (unsigned)b2;
    // ---- classify ----
#pragma unroll
    for (int i = 0; i < 8; i++) {
        int m = tid + i * 256;
        unsigned p16 = vals[i] >> 16;
        if (p16 > P) {
            int slot = atomicAdd(&cnts[0], 1);
            g_idx[r * KNN + slot] = m;
        } else if (p16 == P) {
            int slot = atomicAdd(&cnts[1], 1);
            if (slot < 512)
                cand[slot] =
                    ((unsigned long long)vals[i] << 32) | (unsigned)(0xFFFFFFFFu - m);
        }
    }
    __syncthreads();
    int base = cnts[0], cnt = cnts[1], need = KNN - base;
    if (cnt <= 512) {
        if (tid < 32) {
            for (int it = 0; it < need; it++) {
                unsigned long long best = 0;
                for (int j = tid; j < cnt; j += 32) {
                    unsigned long long k = cand[j];
                    if (k > best) best = k;
                }
#pragma unroll
                for (int s = 16; s; s >>= 1) {
                    unsigned long long o = __shfl_xor_sync(0xffffffffu, best, s);
                    if (o > best) best = o;
                }
                if (tid == 0)
                    g_idx[r * KNN + base + it] =
                        (int)(0xFFFFFFFFu - (unsigned)(best & 0xFFFFFFFFull));
                for (int j = tid; j < cnt; j += 32)
                    if (cand[j] == best) cand[j] = 0;
                __syncwarp();
            }
        }
    } else {
        // exact fallback: block-wide iterative argmax over register values
        bool act[8];
#pragma unroll
        for (int i = 0; i < 8; i++) act[i] = ((vals[i] >> 16) == P);
        for (int it = 0; it < need; it++) {
            unsigned long long best = 0;
#pragma unroll
            for (int i = 0; i < 8; i++)
                if (act[i]) {
                    unsigned long long k = ((unsigned long long)vals[i] << 32) |
                                           (unsigned)(0xFFFFFFFFu - (tid + i * 256));
                    if (k > best) best = k;
                }
            red[tid] = best;
            __syncthreads();
            for (int st = 128; st; st >>= 1) {
                if (tid < st && red[tid + st] > red[tid]) red[tid] = red[tid + st];
                __syncthreads();
            }
            unsigned long long top = red[0];
            int midx = (int)(0xFFFFFFFFu - (unsigned)(top & 0xFFFFFFFFull));
            if (tid == 0) g_idx[r * KNN + base + it] = midx;
            if ((midx & 255) == tid) act[midx >> 8] = false;
            __syncthreads();
        }
    }
}

// ---------------- pack [W1 ; W2-W1] ----------------
__global__ void build_wpq(const float* __restrict__ W, int Cout, int Cin) {
    int i = blockIdx.x * 256 + threadIdx.x;
    if (i >= Cout * Cin) return;
    int o = i / Cin, c = i - o * Cin;
    float w1 = W[(size_t)o * 2 * Cin + c];
    float w2 = W[(size_t)o * 2 * Cin + Cin + c];
    g_Wpq[(size_t)o * Cin + c] = w1;
    g_Wpq[(size_t)(Cout + o) * Cin + c] = w2 - w1;
}

// ---------------- neighbor reduce: partial stats + M = max_k P[nb] + Q ----------------
__global__ void nbr_reduce(int Cout) {
    int o = blockIdx.x, b = blockIdx.y;
    __shared__ float sp[N_PTS];
    __shared__ double rs1[256], rs2[256];
    int tid = threadIdx.x;
    const float* Prow = g_PQ + (size_t)o * NB2 + b * N_PTS;
    const float* Qrow = g_PQ + (size_t)(Cout + o) * NB2 + b * N_PTS;
    for (int i = tid; i < N_PTS; i += 256) sp[i] = Prow[i];
    __syncthreads();
    double s1 = 0.0, s2 = 0.0;
    for (int n = tid; n < N_PTS; n += 256) {
        const int* ip = g_idx + (size_t)(b * N_PTS + n) * KNN;
        float mx = -1e30f, su = 0.f, su2 = 0.f;
#pragma unroll
        for (int k = 0; k < KNN; k++) {
            float p = sp[ip[k]];
            mx = fmaxf(mx, p);
            su += p;
            su2 += p * p;
        }
        float q = Qrow[n];
        g_M[(size_t)o * NB2 + b * N_PTS + n] = mx + q;
        s1 += (double)su + 20.0 * (double)q;
        s2 += (double)su2 + 2.0 * (double)q * (double)su + 20.0 * (double)q * (double)q;
    }
    rs1[tid] = s1;
    rs2[tid] = s2;
    __syncthreads();
    for (int st = 128; st; st >>= 1) {
        if (tid < st) { rs1[tid] += rs1[tid + st]; rs2[tid] += rs2[tid + st]; }
        __syncthreads();
    }
    if (!tid) {
        g_ps[o * 8 + b] = rs1[0];
        g_pq2[o * 8 + b] = rs2[0];
    }
}

__global__ void finalize_bn_edge(const float* __restrict__ gam,
                                 const float* __restrict__ bet, int Cout) {
    int o = blockIdx.x * 256 + threadIdx.x;
    if (o >= Cout) return;
#pragma unroll
    for (int s = 0; s < 2; s++) {
        double su = 0.0, q = 0.0;
        for (int j = 0; j < 4; j++) {
            su += g_ps[o * 8 + s * 4 + j];
            q += g_pq2[o * 8 + s * 4 + j];
        }
        double m = su / (double)PPOS;
        double v = q / (double)PPOS - m * m;
        float sc = (float)((double)gam[o] / sqrt(v + 1e-5));
        g_scale[s * 1024 + o] = sc;
        g_shift[s * 1024 + o] = bet[o] - (float)m * sc;
    }
}

// ---------------- apply BN+LReLU, transpose M -> Ht ----------------
__global__ __launch_bounds__(256) void apply_bn_t(int Cout, int dstoff) {
    __shared__ float tile[32][33];
    int bn0 = blockIdx.x * 32, o0 = blockIdx.y * 32;
    int tx = threadIdx.x & 31, ty = threadIdx.x >> 5;
    int slot = bn0 >> 13;
    const float* sc = g_scale + slot * 1024;
    const float* sh = g_shift + slot * 1024;
#pragma unroll
    for (int r = 0; r < 4; r++) {
        int ol = ty + r * 8;
        int o = o0 + ol;
        float v = g_M[(size_t)o * NB2 + bn0 + tx] * sc[o] + sh[o];
        tile[ol][tx] = v > 0.f ? v : NEG_SLOPE * v;
    }
    __syncthreads();
#pragma unroll
    for (int r = 0; r < 4; r++) {
        int bl = ty + r * 8;
        g_Ht[(size_t)(bn0 + bl) * HCH + dstoff + o0 + tx] = tile[tx][bl];
    }
}

// ---------------- conv5 partial stats ----------------
__global__ void stats_y5() {
    int o = blockIdx.x;
    size_t base = (size_t)o * NB2 + blockIdx.y * 1024;
    double s = 0.0, q = 0.0;
    for (int i = threadIdx.x; i < 1024; i += 256) {
        double v = (double)g_Y5[base + i];
        s += v;
        q += v * v;
    }
    __shared__ double sh[256];
    int tid = threadIdx.x;
    sh[tid] = s;
    __syncthreads();
    for (int st = 128; st; st >>= 1) {
        if (tid < st) sh[tid] += sh[tid + st];
        __syncthreads();
    }
    double ts = sh[0];
    __syncthreads();
    sh[tid] = q;
    __syncthreads();
    for (int st = 128; st; st >>= 1) {
        if (tid < st) sh[tid] += sh[tid + st];
        __syncthreads();
    }
    if (!tid) {
        g_ps[o * 16 + blockIdx.y] = ts;
        g_pq2[o * 16 + blockIdx.y] = sh[0];
    }
}

__global__ void finalize_bn5(const float* __restrict__ gam,
                             const float* __restrict__ bet) {
    int o = blockIdx.x * 256 + threadIdx.x;
    if (o >= 1024) return;
#pragma unroll
    for (int s = 0; s < 2; s++) {
        double su = 0.0, q = 0.0;
        for (int j = 0; j < 8; j++) {
            su += g_ps[o * 16 + s * 8 + j];
            q += g_pq2[o * 16 + s * 8 + j];
        }
        double m = su / 8192.0;
        double v = q / 8192.0 - m * m;
        float sc = (float)((double)gam[o] / sqrt(v + 1e-5));
        g_scale[s * 1024 + o] = sc;
        g_shift[s * 1024 + o] = bet[o] - (float)m * sc;
    }
}

// ---------------- conv5 BN + LReLU + max & mean over N -> z ----------------
__global__ void zmaxmean_kernel() {
    int o = blockIdx.x, b = blockIdx.y;
    int slot = b >> 2;
    const float* row = g_Y5 + (size_t)o * NB2 + (size_t)b * N_PTS;
    float sc = g_scale[slot * 1024 + o], sh = g_shift[slot * 1024 + o];
    float mx = -1e30f, sm = 0.f;
    for (int n = threadIdx.x; n < N_PTS; n += 256) {
        float v = row[n] * sc + sh;
        v = v > 0.f ? v : NEG_SLOPE * v;
        mx = fmaxf(mx, v);
        sm += v;
    }
    __shared__ float smx[256];
    __shared__ float ssm[256];
    int tid = threadIdx.x;
    smx[tid] = mx;
    ssm[tid] = sm;
    __syncthreads();
    for (int st = 128; st; st >>= 1) {
        if (tid < st) {
            smx[tid] = fmaxf(smx[tid], smx[tid + st]);
            ssm[tid] += ssm[tid + st];
        }
        __syncthreads();
    }
    if (!tid) {
        g_z[b * 2048 + o] = smx[0];
        g_z[b * 2048 + 1024 + o] = ssm[0] * (1.f / 2048.f);
    }
}

// ---------------- MLP head ----------------
__global__ void head_kernel(const float* __restrict__ lw1, const float* __restrict__ lb1,
                            const float* __restrict__ lw2, const float* __restrict__ lb2,
                            const float* __restrict__ lw3, const float* __restrict__ lb3,
                            int slot, float* __restrict__ out) {
    int b = blockIdx.x, tid = threadIdx.x;
    __shared__ float zs[2048];
    __shared__ float z1[256];
    __shared__ float z2[64];
    for (int i = tid; i < 2048; i += 256) zs[i] = g_z[(slot * 4 + b) * 2048 + i];
    __syncthreads();
    {
        float a = lb1[tid];
        const float* wr = lw1 + (size_t)tid * 2048;
        for (int c = 0; c < 2048; c++) a += wr[c] * zs[c];
        z1[tid] = a;
    }
    __syncthreads();
    if (tid < 64) {
        float a = lb2[tid];
        const float* wr = lw2 + (size_t)tid * 256;
        for (int c = 0; c < 256; c++) a += wr[c] * z1[c];
        z2[tid] = a;
    }
    __syncthreads();
    if (tid < 10) {
        float a = lb3[tid];
        const float* wr = lw3 + (size_t)tid * 64;
        for (int c = 0; c < 64; c++) a += wr[c] * z2[c];
        g_e[slot * 40 + b * 10 + tid] = a;
        out[6404 + slot * 40 + b * 10 + tid] = a;
    }
}

// ---------------- cluster assignment ----------------
__global__ void cluster_kernel(const float* __restrict__ cw, int slot,
                               float* __restrict__ out) {
    int b = blockIdx.x, j = threadIdx.x;
    __shared__ float es[10];
    __shared__ float red[1024];
    if (j < 10) es[j] = g_e[slot * 40 + b * 10 + j];
    __syncthreads();
    float xd = 0.f, qn = 0.f;
    if (j < 800) {
#pragma unroll
        for (int t = 0; t < 10; t++) {
            float d = es[t] - cw[j * 10 + t];
            xd += d * d;
        }
        qn = 1.f / (1.f + xd);
    }
    red[j] = qn;
    __syncthreads();
    for (int st = 512; st; st >>= 1) {
        if (j < st) red[j] += red[j + st];
        __syncthreads();
    }
    float tot = red[0];
    if (j < 800) {
        out[4 + slot * 3200 + b * 800 + j] = qn / tot;
        if (!slot) out[6484 + b * 800 + j] = xd;
    }
}

__global__ void sim_kernel(float* __restrict__ out) {
    int b = threadIdx.x;
    if (b < 4) {
        float s = 0.f;
        for (int j = 0; j < 10; j++) {
            float d = g_e[b * 10 + j] - g_e[40 + b * 10 + j] + 1e-6f;
            s += d * d;
        }
        out[b] = sqrtf(s);
    }
}

// ---------------- host orchestration (single batched pass) ----------------
extern "C" void kernel_launch(void* const* d_in, const int* in_sizes, int n_in,
                              void* d_out, int out_size) {
    const float* x1 = (const float*)d_in[0];
    const float* x2 = (const float*)d_in[1];
    const float* Wl[4] = {(const float*)d_in[2], (const float*)d_in[5],
                          (const float*)d_in[8], (const float*)d_in[11]};
    const float* Gl[4] = {(const float*)d_in[3], (const float*)d_in[6],
                          (const float*)d_in[9], (const float*)d_in[12]};
    const float* Bl[4] = {(const float*)d_in[4], (const float*)d_in[7],
                          (const float*)d_in[10], (const float*)d_in[13]};
    const float* w5 = (const float*)d_in[14];
    const float* g5 = (const float*)d_in[15];
    const float* b5 = (const float*)d_in[16];
    const float* lw1 = (const float*)d_in[17];
    const float* lb1 = (const float*)d_in[18];
    const float* lw2 = (const float*)d_in[19];
    const float* lb2 = (const float*)d_in[20];
    const float* lw3 = (const float*)d_in[21];
    const float* lb3 = (const float*)d_in[22];
    const float* cw = (const float*)d_in[23];
    float* out = (float*)d_out;

    const int Cin[4] = {3, 64, 64, 128};
    const int Cout[4] = {64, 64, 128, 256};
    const int choff[4] = {0, 0, 64, 128};
    const int dstoff[4] = {0, 64, 128, 256};

    float* xtp = nullptr;
    float* htp = nullptr;
    float* wpq = nullptr;
    float* pq = nullptr;
    float* y5 = nullptr;
    cudaGetSymbolAddress((void**)&xtp, g_Xt);
    cudaGetSymbolAddress((void**)&htp, g_Ht);
    cudaGetSymbolAddress((void**)&wpq, g_Wpq);
    cudaGetSymbolAddress((void**)&pq, g_PQ);
    cudaGetSymbolAddress((void**)&y5, g_Y5);

    split_w5<<<(1024 * HCH + 255) / 256, 256>>>(w5);
    transpose_x<<<NB2 / 256, 256>>>(x1, x2);

    for (int l = 0; l < 4; l++) {
        const float* F = (l == 0) ? xtp : (htp + choff[l]);
        int ldf = (l == 0) ? 4 : HCH;
        int rowLen = (l == 0) ? 4 : Cin[l];
        size_t bstride = (size_t)N_PTS * ldf;
        compute_xx<<<NB2 / 256, 256>>>(F, ldf, Cin[l]);
        pd_gemm2<<<dim3(16, 16, B2), 256>>>(F, ldf, rowLen, Cin[l], bstride);
        topk_kernel<<<NB2, 256>>>();
        build_wpq<<<(Cout[l] * Cin[l] + 255) / 256, 256>>>(Wl[l], Cout[l], Cin[l]);
        sgemm_wn<<<dim3(NB2 / 128, 2 * Cout[l] / 128), 256>>>(wpq, Cin[l], Cin[l], F,
                                                              ldf, rowLen, pq, NB2);
        nbr_reduce<<<dim3(Cout[l], B2), 256>>>(Cout[l]);
        finalize_bn_edge<<<1, 256>>>(Gl[l], Bl[l], Cout[l]);
        apply_bn_t<<<dim3(NB2 / 32, Cout[l] / 32), 256>>>(Cout[l], dstoff[l]);
    }
    split_h<<<(NB2 * HCH + 255) / 256, 256>>>();
    conv5_mma<<<dim3(NB2 / 128, 1024 / 128), 256>>>(y5);
    stats_y5<<<dim3(1024, 16), 256>>>();
    finalize_bn5<<<4, 256>>>(g5, b5);
    zmaxmean_kernel<<<dim3(1024, B2), 256>>>();
    for (int s = 0; s < 2; s++) {
        head_kernel<<<4, 256>>>(lw1, lb1, lw2, lb2, lw3, lb3, s, out);
        cluster_kernel<<<4, 1024>>>(cw, s, out);
    }
    sim_kernel<<<1, 32>>>(out);
}